// round 3
// baseline (speedup 1.0000x reference)
#include <cuda_runtime.h>
#include <math.h>
#include <stdint.h>

// Problem constants
#define DD    400
#define BB    64
#define NC_   10
#define NH_   50
#define NHEAD 20
#define DH    20
#define LL    640      // BB*NC_
#define MM    32000    // BB*NC_*NH_
#define BNH   3200     // BB*NH_

typedef unsigned long long u64;

// ---------------- f32x2 packed math helpers ----------------
__device__ __forceinline__ void fma2(u64& d, u64 a, u64 b) {
    asm("fma.rn.f32x2 %0, %1, %2, %0;" : "+l"(d) : "l"(a), "l"(b));
}
__device__ __forceinline__ u64 pk(float lo, float hi) {
    u64 r; asm("mov.b64 %0, {%1, %2};" : "=l"(r) : "f"(lo), "f"(hi)); return r;
}
__device__ __forceinline__ u64 pk2(float v) {
    u64 r; asm("mov.b64 %0, {%1, %1};" : "=l"(r) : "f"(v)); return r;
}
__device__ __forceinline__ float2 upk(u64 v) {
    float2 r; asm("mov.b64 {%0, %1}, %2;" : "=f"(r.x), "=f"(r.y) : "l"(v)); return r;
}

// ---------------- device scratch (module-static, no runtime alloc) ----------------
__device__ float g_Hcat[BNH * 1200];
__device__ float g_Hp1 [BNH * 400];
__device__ float g_Cc  [LL * 400];
__device__ float g_Hs  [BNH * 400];
__device__ float g_Cs  [LL * 400];
__device__ float g_Hq3 [BNH * 1200];
__device__ float g_Cq3 [LL * 1200];
__device__ float g_WoT [400 * 400];
__device__ float g_Wm  [400 * 400];
__device__ float g_T1  [BNH * 400];
__device__ float g_T2  [LL * 400];
__device__ float g_tc  [400];
__device__ float g_CA  [LL * 400];
__device__ float g_Xo  [MM * 400];
__device__ float g_hall[MM * 400];
__device__ float g_a1  [MM * 400];
__device__ float g_a2  [MM * 200];
__device__ float g_s   [MM];

// ---------------- small prep kernels ----------------
__global__ void build_hcat_kernel(const float* __restrict__ h, float* __restrict__ out) {
    int idx = blockIdx.x * blockDim.x + threadIdx.x;
    if (idx >= BNH * 1200) return;
    int row = idx / 1200, col = idx % 1200;
    int b = row / NH_, j = row % NH_;
    int part = col / 400, d = col % 400;
    int jj = (part == 0) ? (j + NH_ - 1) % NH_ : ((part == 1) ? j : (j + 1) % NH_);
    out[idx] = h[(b * NH_ + jj) * 400 + d];
}

__global__ void transpose400_kernel(const float* __restrict__ Wo, float* __restrict__ WoT) {
    int idx = blockIdx.x * blockDim.x + threadIdx.x;
    if (idx >= 400 * 400) return;
    int r = idx / 400, c = idx % 400;
    WoT[idx] = Wo[c * 400 + r];   // WoT[k][t] = Wo[t][k]
}

__global__ void tc_kernel(const float* __restrict__ b1, const float* __restrict__ bo,
                          const float* __restrict__ b3, const float* __restrict__ W3,
                          float* __restrict__ tc) {
    int r = blockIdx.x * blockDim.x + threadIdx.x;
    if (r >= 400) return;
    float acc = b3[r];
    for (int d = 0; d < 400; d++)
        acc += b1[d] * W3[r * 800 + d] + bo[d] * W3[r * 800 + 400 + d];
    tc[r] = acc;
}

// ---------------- double-buffered SGEMM (f32x2): C(MxN) = A(MxK,lda) @ B(NxK,ldb)^T + epilogue ----------------
// MODE 0: none | 1: +aux0[col] | 2: tanh(x+aux0[col]) | 3: +T1[(b,j)]+T2[(b,i)]+tc[col]
// MODE 4: tanh(x + aux0[(b,i)*N+col])       (modes 3/4 assume M==32000 row layout)
// Requires K % 8 == 0.
#define GBM 128
#define GBN 128
#define GBK 8
#define GTM 8
#define GTN 8

template <int MODE>
__global__ __launch_bounds__(256, 2) void gemm_abt(
    const float* __restrict__ A, int lda,
    const float* __restrict__ B, int ldb,
    float* __restrict__ C, int ldc,
    int M, int N, int K,
    const float* __restrict__ aux0,
    const float* __restrict__ aux1,
    const float* __restrict__ aux2)
{
    __shared__ __align__(16) float As[2][GBK][GBM + 4];
    __shared__ __align__(16) float Bs[2][GBK][GBN + 4];

    int tid = threadIdx.x;
    int tx = tid & 15;          // 0..15 -> 8 cols each
    int ty = tid >> 4;          // 0..15 -> 8 rows each
    int row0 = blockIdx.y * GBM;
    int col0 = blockIdx.x * GBN;

    int lr = tid >> 1;          // 0..127 (row/col within tile for loads)
    int lk = (tid & 1) * 4;     // 0 or 4

    const bool a_ok = (row0 + lr) < M;
    const bool b_ok = (col0 + lr) < N;
    const float* Aptr = A + (size_t)(row0 + lr) * lda + lk;
    const float* Bptr = B + (size_t)(col0 + lr) * ldb + lk;

    u64 accp[GTM][GTN / 2];
    #pragma unroll
    for (int i = 0; i < GTM; i++)
        #pragma unroll
        for (int jp = 0; jp < GTN / 2; jp++) accp[i][jp] = 0ull;

    const float4 f40 = make_float4(0.f, 0.f, 0.f, 0.f);
    float4 va = a_ok ? *reinterpret_cast<const float4*>(Aptr) : f40;
    float4 vb = b_ok ? *reinterpret_cast<const float4*>(Bptr) : f40;
    As[0][lk + 0][lr] = va.x; As[0][lk + 1][lr] = va.y; As[0][lk + 2][lr] = va.z; As[0][lk + 3][lr] = va.w;
    Bs[0][lk + 0][lr] = vb.x; Bs[0][lk + 1][lr] = vb.y; Bs[0][lk + 2][lr] = vb.z; Bs[0][lk + 3][lr] = vb.w;
    __syncthreads();

    const int nt = K / GBK;
    for (int t = 0; t < nt; t++) {
        const int buf = t & 1;
        if (t + 1 < nt) {
            va = a_ok ? *reinterpret_cast<const float4*>(Aptr + (t + 1) * GBK) : f40;
            vb = b_ok ? *reinterpret_cast<const float4*>(Bptr + (t + 1) * GBK) : f40;
        }

        #pragma unroll
        for (int kk = 0; kk < GBK; kk++) {
            const float4* ap = reinterpret_cast<const float4*>(&As[buf][kk][ty * GTM]);
            const float4* bp = reinterpret_cast<const float4*>(&Bs[buf][kk][tx * GTN]);
            float4 a0 = ap[0], a1 = ap[1];
            float4 b0 = bp[0], b1 = bp[1];
            u64 brp[4];
            brp[0] = pk(b0.x, b0.y); brp[1] = pk(b0.z, b0.w);
            brp[2] = pk(b1.x, b1.y); brp[3] = pk(b1.z, b1.w);
            u64 arp[8];
            arp[0] = pk2(a0.x); arp[1] = pk2(a0.y); arp[2] = pk2(a0.z); arp[3] = pk2(a0.w);
            arp[4] = pk2(a1.x); arp[5] = pk2(a1.y); arp[6] = pk2(a1.z); arp[7] = pk2(a1.w);
            #pragma unroll
            for (int i = 0; i < GTM; i++)
                #pragma unroll
                for (int jp = 0; jp < 4; jp++)
                    fma2(accp[i][jp], arp[i], brp[jp]);
        }

        if (t + 1 < nt) {
            const int nb = buf ^ 1;
            As[nb][lk + 0][lr] = va.x; As[nb][lk + 1][lr] = va.y; As[nb][lk + 2][lr] = va.z; As[nb][lk + 3][lr] = va.w;
            Bs[nb][lk + 0][lr] = vb.x; Bs[nb][lk + 1][lr] = vb.y; Bs[nb][lk + 2][lr] = vb.z; Bs[nb][lk + 3][lr] = vb.w;
            __syncthreads();
        }
    }

    #pragma unroll
    for (int i = 0; i < GTM; i++) {
        int r = row0 + ty * GTM + i;
        if (r >= M) continue;
        int bb = r / 500;          // b      (valid for M==32000 modes)
        int ii = (r / 50) % 10;    // i
        int jj = r % 50;           // j
        #pragma unroll
        for (int jp = 0; jp < GTN / 2; jp++) {
            float2 vv = upk(accp[i][jp]);
            #pragma unroll
            for (int q = 0; q < 2; q++) {
                int cidx = col0 + tx * GTN + 2 * jp + q;
                if (cidx >= N) continue;
                float v = (q == 0) ? vv.x : vv.y;
                if (MODE == 1) v += aux0[cidx];
                if (MODE == 2) v = tanhf(v + aux0[cidx]);
                if (MODE == 3) v += aux0[(size_t)(bb * 50 + jj) * N + cidx]
                                 + aux1[(size_t)(bb * 10 + ii) * N + cidx]
                                 + aux2[cidx];
                if (MODE == 4) v = tanhf(v + aux0[(size_t)(bb * 10 + ii) * N + cidx]);
                C[(size_t)r * ldc + cidx] = v;
            }
        }
    }
}

// ---------------- attention (f32x2): one block per (n, head), 2 blocks/SM ----------------
// q[l,n] = Cq3[l, h*20+d] + Hq3[(b(l)*50+n), h*20+d]; k/v at +400/+800.
// No max-subtraction: logits ~ N(0, 0.05), exp is safe.
#define KTILE 128

__global__ __launch_bounds__(640, 2) void attn_kernel(
    const float* __restrict__ Cq3, const float* __restrict__ Hq3,
    float* __restrict__ Xo)
{
    __shared__ __align__(16) float Ks[KTILE * DH];
    __shared__ __align__(16) float Vs[KTILE * DH];

    int n = blockIdx.x / NHEAD;
    int h = blockIdx.x % NHEAD;
    int l = threadIdx.x;              // 640 threads == 640 query rows

    const float scale = 0.22360679774997896f;  // 1/sqrt(20)
    float Z = 0.f;
    int qrow = (l / NC_) * NH_ + n;
    u64 qp[DH / 2];
    u64 accp[DH / 2];
    #pragma unroll
    for (int t = 0; t < DH / 2; t++) {
        float q0 = (Cq3[l * 1200 + h * DH + 2 * t]     + Hq3[qrow * 1200 + h * DH + 2 * t])     * scale;
        float q1 = (Cq3[l * 1200 + h * DH + 2 * t + 1] + Hq3[qrow * 1200 + h * DH + 2 * t + 1]) * scale;
        qp[t] = pk(q0, q1);
        accp[t] = 0ull;
    }

    // Per-thread staging coordinates: 640 float4s per tile (KTILE*DH/4) == blockDim
    const int smm = l / 5;            // key row within tile
    const int st4 = l % 5;            // float4 index within row
    const int soff = h * DH + st4 * 4;

    for (int m0 = 0; m0 < LL; m0 += KTILE) {
        __syncthreads();
        {
            int m = m0 + smm;
            int hr = (m / NC_) * NH_ + n;
            const float4 kc = *reinterpret_cast<const float4*>(Cq3 + m * 1200 + 400 + soff);
            const float4 kh = *reinterpret_cast<const float4*>(Hq3 + hr * 1200 + 400 + soff);
            const float4 vc = *reinterpret_cast<const float4*>(Cq3 + m * 1200 + 800 + soff);
            const float4 vh = *reinterpret_cast<const float4*>(Hq3 + hr * 1200 + 800 + soff);
            *reinterpret_cast<float4*>(Ks + smm * DH + st4 * 4) =
                make_float4(kc.x + kh.x, kc.y + kh.y, kc.z + kh.z, kc.w + kh.w);
            *reinterpret_cast<float4*>(Vs + smm * DH + st4 * 4) =
                make_float4(vc.x + vh.x, vc.y + vh.y, vc.z + vh.z, vc.w + vh.w);
        }
        __syncthreads();

        #pragma unroll 2
        for (int mm = 0; mm < KTILE; mm++) {
            const u64* kp = reinterpret_cast<const u64*>(Ks + mm * DH);
            u64 s0 = 0ull, s1 = 0ull;
            #pragma unroll
            for (int t = 0; t < DH / 2; t++) {
                if (t & 1) fma2(s1, qp[t], kp[t]);
                else       fma2(s0, qp[t], kp[t]);
            }
            float2 xa = upk(s0), xb = upk(s1);
            float e = __expf((xa.x + xa.y) + (xb.x + xb.y));
            Z += e;
            u64 ep = pk2(e);
            const u64* vp = reinterpret_cast<const u64*>(Vs + mm * DH);
            #pragma unroll
            for (int t = 0; t < DH / 2; t++)
                fma2(accp[t], ep, vp[t]);
        }
    }

    float iz = 1.f / Z;
    float* out = Xo + ((size_t)l * NH_ + n) * 400 + h * DH;
    #pragma unroll
    for (int t = 0; t < DH / 2; t++) {
        float2 vv = upk(accp[t]);
        out[2 * t]     = vv.x * iz;
        out[2 * t + 1] = vv.y * iz;
    }
}

// ---------------- score: s[m] = a2[m,:]·Wa3 + ba3 ----------------
__global__ void score_kernel(const float* __restrict__ a2, const float* __restrict__ Wa3,
                             const float* __restrict__ ba3, float* __restrict__ s)
{
    int row = blockIdx.x * 8 + threadIdx.y;
    if (row >= MM) return;
    int lane = threadIdx.x;
    float acc = 0.f;
    for (int d = lane; d < 200; d += 32) acc += a2[(size_t)row * 200 + d] * Wa3[d];
    #pragma unroll
    for (int o = 16; o > 0; o >>= 1) acc += __shfl_xor_sync(0xffffffffu, acc, o);
    if (lane == 0) s[row] = acc + ba3[0];
}

// ---------------- softmax over j + weighted sum -> u ----------------
__global__ void softmax_u_kernel(const float* __restrict__ s, const float* __restrict__ hall,
                                 float* __restrict__ u)
{
    __shared__ float a[NH_];
    int bi = blockIdx.x;      // 0..639
    if (threadIdx.x == 0) {
        float mx = -1e30f;
        for (int j = 0; j < NH_; j++) mx = fmaxf(mx, s[bi * NH_ + j]);
        float Z = 0.f;
        for (int j = 0; j < NH_; j++) { float e = __expf(s[bi * NH_ + j] - mx); a[j] = e; Z += e; }
        float iz = 1.f / Z;
        for (int j = 0; j < NH_; j++) a[j] *= iz;
    }
    __syncthreads();
    for (int d = threadIdx.x; d < 400; d += blockDim.x) {
        float acc = 0.f;
        for (int j = 0; j < NH_; j++)
            acc += a[j] * hall[((size_t)bi * NH_ + j) * 400 + d];
        u[(size_t)bi * 400 + d] = acc;
    }
}

// ---------------- launch ----------------
static inline dim3 ggrid(int M, int N) { return dim3((N + GBN - 1) / GBN, (M + GBM - 1) / GBM); }

extern "C" void kernel_launch(void* const* d_in, const int* in_sizes, int n_in,
                              void* d_out, int out_size)
{
    const float* h    = (const float*)d_in[0];
    const float* c    = (const float*)d_in[2];
    const float* W1   = (const float*)d_in[4];
    const float* b1   = (const float*)d_in[5];
    const float* W2   = (const float*)d_in[6];
    const float* b2   = (const float*)d_in[7];
    const float* W3   = (const float*)d_in[8];
    const float* b3   = (const float*)d_in[9];
    const float* Wa1  = (const float*)d_in[10];
    const float* ba1  = (const float*)d_in[11];
    const float* Wa2  = (const float*)d_in[12];
    const float* ba2  = (const float*)d_in[13];
    const float* Wa3  = (const float*)d_in[14];
    const float* ba3  = (const float*)d_in[15];
    const float* Wqkv = (const float*)d_in[16];
    const float* bqkv = (const float*)d_in[17];
    const float* Wo   = (const float*)d_in[18];
    const float* bo   = (const float*)d_in[19];
    float* u = (float*)d_out;

    float *Hcat, *Hp1, *Cc, *Hs, *Cs, *Hq3, *Cq3, *WoT, *Wm, *T1, *T2, *tc, *CA, *Xo, *hall, *a1, *a2, *sc;
    cudaGetSymbolAddress((void**)&Hcat, g_Hcat);
    cudaGetSymbolAddress((void**)&Hp1,  g_Hp1);
    cudaGetSymbolAddress((void**)&Cc,   g_Cc);
    cudaGetSymbolAddress((void**)&Hs,   g_Hs);
    cudaGetSymbolAddress((void**)&Cs,   g_Cs);
    cudaGetSymbolAddress((void**)&Hq3,  g_Hq3);
    cudaGetSymbolAddress((void**)&Cq3,  g_Cq3);
    cudaGetSymbolAddress((void**)&WoT,  g_WoT);
    cudaGetSymbolAddress((void**)&Wm,   g_Wm);
    cudaGetSymbolAddress((void**)&T1,   g_T1);
    cudaGetSymbolAddress((void**)&T2,   g_T2);
    cudaGetSymbolAddress((void**)&tc,   g_tc);
    cudaGetSymbolAddress((void**)&CA,   g_CA);
    cudaGetSymbolAddress((void**)&Xo,   g_Xo);
    cudaGetSymbolAddress((void**)&hall, g_hall);
    cudaGetSymbolAddress((void**)&a1,   g_a1);
    cudaGetSymbolAddress((void**)&a2,   g_a2);
    cudaGetSymbolAddress((void**)&sc,   g_s);

    // prep
    build_hcat_kernel<<<(BNH * 1200 + 255) / 256, 256>>>(h, Hcat);
    transpose400_kernel<<<(400 * 400 + 255) / 256, 256>>>(Wo, WoT);
    tc_kernel<<<2, 256>>>(b1, bo, b3, W3, tc);

    // decomposed small GEMMs
    gemm_abt<0><<<ggrid(BNH, 400), 256>>>(Hcat, 1200, W1, 1600, Hp1, 400, BNH, 400, 1200, nullptr, nullptr, nullptr);
    gemm_abt<0><<<ggrid(LL, 400),  256>>>(c, 400, W1 + 1200, 1600, Cc, 400, LL, 400, 400, nullptr, nullptr, nullptr);
    gemm_abt<0><<<ggrid(BNH, 400), 256>>>(h, 400, W2 + 400, 800, Hs, 400, BNH, 400, 400, nullptr, nullptr, nullptr);
    gemm_abt<1><<<ggrid(LL, 400),  256>>>(c, 400, W2, 800, Cs, 400, LL, 400, 400, b2, nullptr, nullptr);
    gemm_abt<0><<<ggrid(BNH, 1200), 256>>>(Hs, 400, Wqkv, 400, Hq3, 1200, BNH, 1200, 400, nullptr, nullptr, nullptr);
    gemm_abt<1><<<ggrid(LL, 1200),  256>>>(Cs, 400, Wqkv, 400, Cq3, 1200, LL, 1200, 400, bqkv, nullptr, nullptr);
    gemm_abt<0><<<ggrid(400, 400), 256>>>(W3 + 400, 800, WoT, 400, Wm, 400, 400, 400, 400, nullptr, nullptr, nullptr);
    gemm_abt<0><<<ggrid(BNH, 400), 256>>>(Hp1, 400, W3, 800, T1, 400, BNH, 400, 400, nullptr, nullptr, nullptr);
    gemm_abt<0><<<ggrid(LL, 400),  256>>>(Cc, 400, W3, 800, T2, 400, LL, 400, 400, nullptr, nullptr, nullptr);
    gemm_abt<1><<<ggrid(LL, 400),  256>>>(c, 400, Wa1 + 400, 800, CA, 400, LL, 400, 400, ba1, nullptr, nullptr);

    // attention (1000 blocks = 50 n x 20 heads)
    attn_kernel<<<NH_ * NHEAD, 640>>>(Cq3, Hq3, Xo);

    // big fused GEMMs
    gemm_abt<3><<<ggrid(MM, 400), 256>>>(Xo, 400, Wm, 400, hall, 400, MM, 400, 400, T1, T2, tc);
    gemm_abt<4><<<ggrid(MM, 400), 256>>>(hall, 400, Wa1, 800, a1, 400, MM, 400, 400, CA, nullptr, nullptr);
    gemm_abt<2><<<ggrid(MM, 200), 256>>>(a1, 400, Wa2, 400, a2, 200, MM, 200, 400, ba2, nullptr, nullptr);

    // scoring + softmax + weighted sum
    score_kernel<<<MM / 8, dim3(32, 8)>>>(a2, Wa3, ba3, sc);
    softmax_u_kernel<<<LL, 128>>>(sc, hall, u);
}

// round 4
// speedup vs baseline: 1.5470x; 1.5470x over previous
#include <cuda_runtime.h>
#include <cuda_bf16.h>
#include <math.h>
#include <stdint.h>

// Problem constants
#define DD    400
#define BB    64
#define NC_   10
#define NH_   50
#define NHEAD 20
#define DH    20
#define LL    640      // BB*NC_
#define MM    32000    // BB*NC_*NH_
#define BNH   3200     // BB*NH_

typedef __nv_bfloat16 bf16;

// ---------------- fp32 device scratch ----------------
__device__ float g_Hcat[BNH * 1200];
__device__ float g_Hp1 [BNH * 400];
__device__ float g_Cc  [LL * 400];
__device__ float g_Hs  [BNH * 400];
__device__ float g_Cs  [LL * 400];
__device__ float g_Hq3 [BNH * 1200];
__device__ float g_Cq3 [LL * 1200];
__device__ float g_WoT [400 * 400];
__device__ float g_Wm  [400 * 400];
__device__ float g_T1  [BNH * 400];
__device__ float g_T2  [LL * 400];
__device__ float g_tc  [400];
__device__ float g_CA  [LL * 400];
__device__ float g_Xo  [MM * 400];
__device__ float g_hall[MM * 400];
__device__ float g_a1  [MM * 400];
__device__ float g_a2  [MM * 200];
__device__ float g_s   [MM];

// ---------------- bf16 split scratch (hi/lo pairs) ----------------
__device__ __align__(16) bf16 g_bHcat_h[BNH * 1200], g_bHcat_l[BNH * 1200];
__device__ __align__(16) bf16 g_bh_h  [BNH * 400],  g_bh_l  [BNH * 400];
__device__ __align__(16) bf16 g_bHs_h [BNH * 400],  g_bHs_l [BNH * 400];
__device__ __align__(16) bf16 g_bHp1_h[BNH * 400],  g_bHp1_l[BNH * 400];
__device__ __align__(16) bf16 g_bXo_h [MM * 400],   g_bXo_l [MM * 400];
__device__ __align__(16) bf16 g_bhall_h[MM * 400],  g_bhall_l[MM * 400];
__device__ __align__(16) bf16 g_ba1_h [MM * 400],   g_ba1_l [MM * 400];
__device__ __align__(16) bf16 g_bW1_h [400 * 1600], g_bW1_l [400 * 1600];
__device__ __align__(16) bf16 g_bW2_h [400 * 800],  g_bW2_l [400 * 800];
__device__ __align__(16) bf16 g_bWqkv_h[1200 * 400],g_bWqkv_l[1200 * 400];
__device__ __align__(16) bf16 g_bW3_h [400 * 800],  g_bW3_l [400 * 800];
__device__ __align__(16) bf16 g_bWa1_h[400 * 800],  g_bWa1_l[400 * 800];
__device__ __align__(16) bf16 g_bWa2_h[200 * 400],  g_bWa2_l[200 * 400];
__device__ __align__(16) bf16 g_bWm_h [400 * 400],  g_bWm_l [400 * 400];

// ---------------- small prep kernels ----------------
__global__ void build_hcat_kernel(const float* __restrict__ h, float* __restrict__ out) {
    int idx = blockIdx.x * blockDim.x + threadIdx.x;
    if (idx >= BNH * 1200) return;
    int row = idx / 1200, col = idx % 1200;
    int b = row / NH_, j = row % NH_;
    int part = col / 400, d = col % 400;
    int jj = (part == 0) ? (j + NH_ - 1) % NH_ : ((part == 1) ? j : (j + 1) % NH_);
    out[idx] = h[(b * NH_ + jj) * 400 + d];
}

__global__ void transpose400_kernel(const float* __restrict__ Wo, float* __restrict__ WoT) {
    int idx = blockIdx.x * blockDim.x + threadIdx.x;
    if (idx >= 400 * 400) return;
    int r = idx / 400, c = idx % 400;
    WoT[idx] = Wo[c * 400 + r];
}

__global__ void tc_kernel(const float* __restrict__ b1, const float* __restrict__ bo,
                          const float* __restrict__ b3, const float* __restrict__ W3,
                          float* __restrict__ tc) {
    int r = blockIdx.x * blockDim.x + threadIdx.x;
    if (r >= 400) return;
    float acc = b3[r];
    for (int d = 0; d < 400; d++)
        acc += b1[d] * W3[r * 800 + d] + bo[d] * W3[r * 800 + 400 + d];
    tc[r] = acc;
}

// split fp32 -> bf16 hi + bf16 lo
__global__ void convert_split_kernel(const float* __restrict__ x,
                                     bf16* __restrict__ hi, bf16* __restrict__ lo, int n) {
    int i = blockIdx.x * blockDim.x + threadIdx.x;
    if (i >= n) return;
    float v = x[i];
    bf16 hh = __float2bfloat16_rn(v);
    float r = v - __bfloat162float(hh);
    hi[i] = hh;
    lo[i] = __float2bfloat16_rn(r);
}

// ---------------- tensor-core GEMM (bf16 2-way split, 3 MMAs) ----------------
// C(MxN) = A(MxK) @ B(NxK)^T + epilogue, where A = Ah+Al, B = Bh+Bl (bf16 split)
// Requires: M % 128 == 0, K % 16 == 0, lda/ldb element counts give 16B-aligned rows.
// MODE 0: none | 2: tanh(x+aux0[col]) | 3: +aux0[(b,j)]+aux1[(b,i)]+aux2[col]
// MODE 4: tanh(x + aux0[(b,i)*N+col])   (modes 3/4 assume MM row layout)
#define TBM 128
#define TBN 128
#define TBK 16
#define SSTR 24   // smem row stride in bf16 elems (48B -> conflict-free ldmatrix)

__device__ __forceinline__ uint32_t s2u(const void* p) {
    return (uint32_t)__cvta_generic_to_shared(p);
}
__device__ __forceinline__ void ldm4(uint32_t& r0, uint32_t& r1, uint32_t& r2, uint32_t& r3,
                                     uint32_t addr) {
    asm volatile("ldmatrix.sync.aligned.m8n8.x4.shared.b16 {%0,%1,%2,%3}, [%4];"
                 : "=r"(r0), "=r"(r1), "=r"(r2), "=r"(r3) : "r"(addr));
}
__device__ __forceinline__ void mma16816(float* d, const uint32_t* a, uint32_t b0, uint32_t b1) {
    asm volatile("mma.sync.aligned.m16n8k16.row.col.f32.bf16.bf16.f32 "
                 "{%0,%1,%2,%3}, {%4,%5,%6,%7}, {%8,%9}, {%0,%1,%2,%3};"
                 : "+f"(d[0]), "+f"(d[1]), "+f"(d[2]), "+f"(d[3])
                 : "r"(a[0]), "r"(a[1]), "r"(a[2]), "r"(a[3]), "r"(b0), "r"(b1));
}

template <int MODE>
__global__ __launch_bounds__(256) void gemm_mma(
    const bf16* __restrict__ Ah, const bf16* __restrict__ Al, int lda,
    const bf16* __restrict__ Bh, const bf16* __restrict__ Bl, int ldb,
    float* __restrict__ C, int ldc, int M, int N, int K,
    const float* __restrict__ aux0, const float* __restrict__ aux1,
    const float* __restrict__ aux2)
{
    __shared__ __align__(16) bf16 sAh[2][TBM * SSTR];
    __shared__ __align__(16) bf16 sAl[2][TBM * SSTR];
    __shared__ __align__(16) bf16 sBh[2][TBM * SSTR];
    __shared__ __align__(16) bf16 sBl[2][TBM * SSTR];

    const int tid = threadIdx.x;
    const int lrow = tid >> 1, lhalf = tid & 1;
    const int row0 = blockIdx.y * TBM, col0 = blockIdx.x * TBN;

    const bool bok = (col0 + lrow) < N;
    const int brow = bok ? (col0 + lrow) : 0;
    const bf16* Aph = Ah + (size_t)(row0 + lrow) * lda + lhalf * 8;
    const bf16* Apl = Al + (size_t)(row0 + lrow) * lda + lhalf * 8;
    const bf16* Bph = Bh + (size_t)brow * ldb + lhalf * 8;
    const bf16* Bpl = Bl + (size_t)brow * ldb + lhalf * 8;
    const int sidx = lrow * SSTR + lhalf * 8;

    const int w = tid >> 5, lane = tid & 31;
    const int wm = w >> 2, wn = w & 3;
    const int mrow = ((lane >> 3) & 1) * 8 + (lane & 7);
    const int koff = (lane >> 4) * 8;

    uint32_t aoff[4], boff[2];
    #pragma unroll
    for (int fm = 0; fm < 4; fm++)
        aoff[fm] = (uint32_t)(((wm * 64 + fm * 16 + mrow) * SSTR + koff) * 2);
    #pragma unroll
    for (int f = 0; f < 2; f++)
        boff[f] = (uint32_t)(((wn * 32 + f * 16 + mrow) * SSTR + koff) * 2);

    const uint32_t bAh = s2u(sAh), bAl = s2u(sAl), bBh = s2u(sBh), bBl = s2u(sBl);
    const uint32_t STB = TBM * SSTR * 2;   // bytes per stage

    float acc[4][4][4];
    #pragma unroll
    for (int i = 0; i < 4; i++)
        #pragma unroll
        for (int j = 0; j < 4; j++)
            #pragma unroll
            for (int e = 0; e < 4; e++) acc[i][j][e] = 0.f;

    const uint4 z4 = make_uint4(0u, 0u, 0u, 0u);

    // initial stage 0 load (k = 0)
    {
        uint4 vah = *reinterpret_cast<const uint4*>(Aph);
        uint4 val = *reinterpret_cast<const uint4*>(Apl);
        uint4 vbh = bok ? *reinterpret_cast<const uint4*>(Bph) : z4;
        uint4 vbl = bok ? *reinterpret_cast<const uint4*>(Bpl) : z4;
        *reinterpret_cast<uint4*>(&sAh[0][sidx]) = vah;
        *reinterpret_cast<uint4*>(&sAl[0][sidx]) = val;
        *reinterpret_cast<uint4*>(&sBh[0][sidx]) = vbh;
        *reinterpret_cast<uint4*>(&sBl[0][sidx]) = vbl;
    }
    __syncthreads();

    const int nk = K / TBK;
    for (int t = 0; t < nk; t++) {
        const int st = t & 1;
        uint4 vah, val, vbh, vbl;
        if (t + 1 < nk) {
            const int k = (t + 1) * TBK;
            vah = *reinterpret_cast<const uint4*>(Aph + k);
            val = *reinterpret_cast<const uint4*>(Apl + k);
            vbh = bok ? *reinterpret_cast<const uint4*>(Bph + k) : z4;
            vbl = bok ? *reinterpret_cast<const uint4*>(Bpl + k) : z4;
        }

        // fragments
        uint32_t ah[4][4], al[4][4], bh[2][4], bl[2][4];
        #pragma unroll
        for (int fm = 0; fm < 4; fm++) {
            ldm4(ah[fm][0], ah[fm][1], ah[fm][2], ah[fm][3], bAh + st * STB + aoff[fm]);
            ldm4(al[fm][0], al[fm][1], al[fm][2], al[fm][3], bAl + st * STB + aoff[fm]);
        }
        #pragma unroll
        for (int f = 0; f < 2; f++) {
            ldm4(bh[f][0], bh[f][1], bh[f][2], bh[f][3], bBh + st * STB + boff[f]);
            ldm4(bl[f][0], bl[f][1], bl[f][2], bl[f][3], bBl + st * STB + boff[f]);
        }

        #pragma unroll
        for (int fm = 0; fm < 4; fm++) {
            #pragma unroll
            for (int f = 0; f < 2; f++) {
                // n8 sub-block 0: B regs {0,2}; sub-block 1: {1,3}
                mma16816(acc[fm][f * 2 + 0], ah[fm], bh[f][0], bh[f][2]);
                mma16816(acc[fm][f * 2 + 0], ah[fm], bl[f][0], bl[f][2]);
                mma16816(acc[fm][f * 2 + 0], al[fm], bh[f][0], bh[f][2]);
                mma16816(acc[fm][f * 2 + 1], ah[fm], bh[f][1], bh[f][3]);
                mma16816(acc[fm][f * 2 + 1], ah[fm], bl[f][1], bl[f][3]);
                mma16816(acc[fm][f * 2 + 1], al[fm], bh[f][1], bh[f][3]);
            }
        }

        if (t + 1 < nk) {
            const int ns = st ^ 1;
            *reinterpret_cast<uint4*>(&sAh[ns][sidx]) = vah;
            *reinterpret_cast<uint4*>(&sAl[ns][sidx]) = val;
            *reinterpret_cast<uint4*>(&sBh[ns][sidx]) = vbh;
            *reinterpret_cast<uint4*>(&sBl[ns][sidx]) = vbl;
            __syncthreads();
        }
    }

    // epilogue
    #pragma unroll
    for (int fm = 0; fm < 4; fm++) {
        const int rb = row0 + wm * 64 + fm * 16 + (lane >> 2);
        #pragma unroll
        for (int fn = 0; fn < 4; fn++) {
            const int cb = col0 + wn * 32 + fn * 8 + (lane & 3) * 2;
            #pragma unroll
            for (int e = 0; e < 4; e++) {
                const int r = rb + ((e >> 1) * 8);
                const int cc = cb + (e & 1);
                if (cc >= N) continue;
                float v = acc[fm][fn][e];
                if (MODE == 2) v = tanhf(v + aux0[cc]);
                if (MODE == 3) {
                    int bb = r / 500, ii = (r / 50) % 10, jj = r % 50;
                    v += aux0[(size_t)(bb * 50 + jj) * N + cc]
                       + aux1[(size_t)(bb * 10 + ii) * N + cc]
                       + aux2[cc];
                }
                if (MODE == 4) {
                    int bb = r / 500, ii = (r / 50) % 10;
                    v = tanhf(v + aux0[(size_t)(bb * 10 + ii) * N + cc]);
                }
                C[(size_t)r * ldc + cc] = v;
            }
        }
    }
}

// ---------------- scalar double-buffered SGEMM (for small LL-row GEMMs) ----------------
// MODE 0: none | 1: +aux0[col]
#define GBM 128
#define GBN 128
#define GBK 8
#define GTM 8
#define GTN 8

template <int MODE>
__global__ __launch_bounds__(256, 2) void gemm_abt(
    const float* __restrict__ A, int lda,
    const float* __restrict__ B, int ldb,
    float* __restrict__ C, int ldc,
    int M, int N, int K,
    const float* __restrict__ aux0)
{
    __shared__ float As[2][GBK][GBM + 4];
    __shared__ float Bs[2][GBK][GBN + 4];

    int tid = threadIdx.x;
    int tx = tid & 15;
    int ty = tid >> 4;
    int row0 = blockIdx.y * GBM;
    int col0 = blockIdx.x * GBN;

    int lr = tid >> 1;
    int lk = (tid & 1) * 4;

    const bool a_ok = (row0 + lr) < M;
    const bool b_ok = (col0 + lr) < N;
    const float* Aptr = A + (size_t)(row0 + lr) * lda + lk;
    const float* Bptr = B + (size_t)(col0 + lr) * ldb + lk;

    float acc[GTM][GTN];
    #pragma unroll
    for (int i = 0; i < GTM; i++)
        #pragma unroll
        for (int j = 0; j < GTN; j++) acc[i][j] = 0.f;

    const float4 f40 = make_float4(0.f, 0.f, 0.f, 0.f);
    float4 va = a_ok ? *reinterpret_cast<const float4*>(Aptr) : f40;
    float4 vb = b_ok ? *reinterpret_cast<const float4*>(Bptr) : f40;
    As[0][lk + 0][lr] = va.x; As[0][lk + 1][lr] = va.y; As[0][lk + 2][lr] = va.z; As[0][lk + 3][lr] = va.w;
    Bs[0][lk + 0][lr] = vb.x; Bs[0][lk + 1][lr] = vb.y; Bs[0][lk + 2][lr] = vb.z; Bs[0][lk + 3][lr] = vb.w;
    __syncthreads();

    const int nt = K / GBK;
    for (int t = 0; t < nt; t++) {
        const int buf = t & 1;
        if (t + 1 < nt) {
            va = a_ok ? *reinterpret_cast<const float4*>(Aptr + (t + 1) * GBK) : f40;
            vb = b_ok ? *reinterpret_cast<const float4*>(Bptr + (t + 1) * GBK) : f40;
        }

        #pragma unroll
        for (int kk = 0; kk < GBK; kk++) {
            float ar[GTM], br[GTN];
            const float4* ap = reinterpret_cast<const float4*>(&As[buf][kk][ty * GTM]);
            const float4* bp = reinterpret_cast<const float4*>(&Bs[buf][kk][tx * GTN]);
            float4 a0 = ap[0], a1 = ap[1];
            float4 b0 = bp[0], b1 = bp[1];
            ar[0]=a0.x; ar[1]=a0.y; ar[2]=a0.z; ar[3]=a0.w; ar[4]=a1.x; ar[5]=a1.y; ar[6]=a1.z; ar[7]=a1.w;
            br[0]=b0.x; br[1]=b0.y; br[2]=b0.z; br[3]=b0.w; br[4]=b1.x; br[5]=b1.y; br[6]=b1.z; br[7]=b1.w;
            #pragma unroll
            for (int i = 0; i < GTM; i++)
                #pragma unroll
                for (int j = 0; j < GTN; j++)
                    acc[i][j] += ar[i] * br[j];
        }

        if (t + 1 < nt) {
            const int nb = buf ^ 1;
            As[nb][lk + 0][lr] = va.x; As[nb][lk + 1][lr] = va.y; As[nb][lk + 2][lr] = va.z; As[nb][lk + 3][lr] = va.w;
            Bs[nb][lk + 0][lr] = vb.x; Bs[nb][lk + 1][lr] = vb.y; Bs[nb][lk + 2][lr] = vb.z; Bs[nb][lk + 3][lr] = vb.w;
            __syncthreads();
        }
    }

    #pragma unroll
    for (int i = 0; i < GTM; i++) {
        int r = row0 + ty * GTM + i;
        if (r >= M) continue;
        #pragma unroll
        for (int j = 0; j < GTN; j++) {
            int cidx = col0 + tx * GTN + j;
            if (cidx >= N) continue;
            float v = acc[i][j];
            if (MODE == 1) v += aux0[cidx];
            C[(size_t)r * ldc + cidx] = v;
        }
    }
}

// ---------------- attention: one block per (n, head), 2 blocks/SM ----------------
#define KTILE 128

__global__ __launch_bounds__(640, 2) void attn_kernel(
    const float* __restrict__ Cq3, const float* __restrict__ Hq3,
    float* __restrict__ Xo)
{
    __shared__ __align__(16) float Ks[KTILE * DH];
    __shared__ __align__(16) float Vs[KTILE * DH];

    int n = blockIdx.x / NHEAD;
    int h = blockIdx.x % NHEAD;
    int l = threadIdx.x;

    const float scale = 0.22360679774997896f;  // 1/sqrt(20)
    float q[DH], acc[DH];
    float Z = 0.f;
    int qrow = (l / NC_) * NH_ + n;
    #pragma unroll
    for (int d = 0; d < DH; d++) {
        q[d] = (Cq3[l * 1200 + h * DH + d] + Hq3[qrow * 1200 + h * DH + d]) * scale;
        acc[d] = 0.f;
    }

    const int smm = l / 5;
    const int st4 = l % 5;
    const int soff = h * DH + st4 * 4;

    for (int m0 = 0; m0 < LL; m0 += KTILE) {
        __syncthreads();
        {
            int m = m0 + smm;
            int hr = (m / NC_) * NH_ + n;
            const float4 kc = *reinterpret_cast<const float4*>(Cq3 + m * 1200 + 400 + soff);
            const float4 kh = *reinterpret_cast<const float4*>(Hq3 + hr * 1200 + 400 + soff);
            const float4 vc = *reinterpret_cast<const float4*>(Cq3 + m * 1200 + 800 + soff);
            const float4 vh = *reinterpret_cast<const float4*>(Hq3 + hr * 1200 + 800 + soff);
            *reinterpret_cast<float4*>(Ks + smm * DH + st4 * 4) =
                make_float4(kc.x + kh.x, kc.y + kh.y, kc.z + kh.z, kc.w + kh.w);
            *reinterpret_cast<float4*>(Vs + smm * DH + st4 * 4) =
                make_float4(vc.x + vh.x, vc.y + vh.y, vc.z + vh.z, vc.w + vh.w);
        }
        __syncthreads();

        #pragma unroll 2
        for (int mm = 0; mm < KTILE; mm++) {
            const float4* kp = reinterpret_cast<const float4*>(Ks + mm * DH);
            float s0 = 0.f, s1 = 0.f;
            #pragma unroll
            for (int t = 0; t < 5; t++) {
                float4 kv = kp[t];
                if (t & 1) { s1 += q[4*t]*kv.x + q[4*t+1]*kv.y + q[4*t+2]*kv.z + q[4*t+3]*kv.w; }
                else       { s0 += q[4*t]*kv.x + q[4*t+1]*kv.y + q[4*t+2]*kv.z + q[4*t+3]*kv.w; }
            }
            float e = __expf(s0 + s1);
            Z += e;
            const float4* vp = reinterpret_cast<const float4*>(Vs + mm * DH);
            #pragma unroll
            for (int t = 0; t < 5; t++) {
                float4 vv = vp[t];
                acc[4*t]   += e * vv.x;
                acc[4*t+1] += e * vv.y;
                acc[4*t+2] += e * vv.z;
                acc[4*t+3] += e * vv.w;
            }
        }
    }

    float iz = 1.f / Z;
    float* out = Xo + ((size_t)l * NH_ + n) * 400 + h * DH;
    #pragma unroll
    for (int d = 0; d < DH; d++) out[d] = acc[d] * iz;
}

// ---------------- score: s[m] = a2[m,:]·Wa3 + ba3 ----------------
__global__ void score_kernel(const float* __restrict__ a2, const float* __restrict__ Wa3,
                             const float* __restrict__ ba3, float* __restrict__ s)
{
    int row = blockIdx.x * 8 + threadIdx.y;
    if (row >= MM) return;
    int lane = threadIdx.x;
    float acc = 0.f;
    for (int d = lane; d < 200; d += 32) acc += a2[(size_t)row * 200 + d] * Wa3[d];
    #pragma unroll
    for (int o = 16; o > 0; o >>= 1) acc += __shfl_xor_sync(0xffffffffu, acc, o);
    if (lane == 0) s[row] = acc + ba3[0];
}

// ---------------- softmax over j + weighted sum -> u ----------------
__global__ void softmax_u_kernel(const float* __restrict__ s, const float* __restrict__ hall,
                                 float* __restrict__ u)
{
    __shared__ float a[NH_];
    int bi = blockIdx.x;
    if (threadIdx.x == 0) {
        float mx = -1e30f;
        for (int j = 0; j < NH_; j++) mx = fmaxf(mx, s[bi * NH_ + j]);
        float Z = 0.f;
        for (int j = 0; j < NH_; j++) { float e = __expf(s[bi * NH_ + j] - mx); a[j] = e; Z += e; }
        float iz = 1.f / Z;
        for (int j = 0; j < NH_; j++) a[j] *= iz;
    }
    __syncthreads();
    for (int d = threadIdx.x; d < 400; d += blockDim.x) {
        float acc = 0.f;
        for (int j = 0; j < NH_; j++)
            acc += a[j] * hall[((size_t)bi * NH_ + j) * 400 + d];
        u[(size_t)bi * 400 + d] = acc;
    }
}

// ---------------- launch ----------------
static inline dim3 ggrid(int M, int N) { return dim3((N + GBN - 1) / GBN, (M + GBM - 1) / GBM); }
static inline void conv(const float* x, bf16* hi, bf16* lo, int n) {
    convert_split_kernel<<<(n + 255) / 256, 256>>>(x, hi, lo, n);
}

extern "C" void kernel_launch(void* const* d_in, const int* in_sizes, int n_in,
                              void* d_out, int out_size)
{
    const float* h    = (const float*)d_in[0];
    const float* c    = (const float*)d_in[2];
    const float* W1   = (const float*)d_in[4];
    const float* b1   = (const float*)d_in[5];
    const float* W2   = (const float*)d_in[6];
    const float* b2   = (const float*)d_in[7];
    const float* W3   = (const float*)d_in[8];
    const float* b3   = (const float*)d_in[9];
    const float* Wa1  = (const float*)d_in[10];
    const float* ba1  = (const float*)d_in[11];
    const float* Wa2  = (const float*)d_in[12];
    const float* ba2  = (const float*)d_in[13];
    const float* Wa3  = (const float*)d_in[14];
    const float* ba3  = (const float*)d_in[15];
    const float* Wqkv = (const float*)d_in[16];
    const float* bqkv = (const float*)d_in[17];
    const float* Wo   = (const float*)d_in[18];
    const float* bo   = (const float*)d_in[19];
    float* u = (float*)d_out;

    float *Hcat, *Hp1, *Cc, *Hs, *Cs, *Hq3, *Cq3, *WoT, *Wm, *T1, *T2, *tc, *CA, *Xo, *hall, *a1, *a2, *sc;
    cudaGetSymbolAddress((void**)&Hcat, g_Hcat);
    cudaGetSymbolAddress((void**)&Hp1,  g_Hp1);
    cudaGetSymbolAddress((void**)&Cc,   g_Cc);
    cudaGetSymbolAddress((void**)&Hs,   g_Hs);
    cudaGetSymbolAddress((void**)&Cs,   g_Cs);
    cudaGetSymbolAddress((void**)&Hq3,  g_Hq3);
    cudaGetSymbolAddress((void**)&Cq3,  g_Cq3);
    cudaGetSymbolAddress((void**)&WoT,  g_WoT);
    cudaGetSymbolAddress((void**)&Wm,   g_Wm);
    cudaGetSymbolAddress((void**)&T1,   g_T1);
    cudaGetSymbolAddress((void**)&T2,   g_T2);
    cudaGetSymbolAddress((void**)&tc,   g_tc);
    cudaGetSymbolAddress((void**)&CA,   g_CA);
    cudaGetSymbolAddress((void**)&Xo,   g_Xo);
    cudaGetSymbolAddress((void**)&hall, g_hall);
    cudaGetSymbolAddress((void**)&a1,   g_a1);
    cudaGetSymbolAddress((void**)&a2,   g_a2);
    cudaGetSymbolAddress((void**)&sc,   g_s);

    bf16 *bHcat_h, *bHcat_l, *bh_h, *bh_l, *bHs_h, *bHs_l, *bHp1_h, *bHp1_l;
    bf16 *bXo_h, *bXo_l, *bhall_h, *bhall_l, *ba1_h, *ba1_l;
    bf16 *bW1_h, *bW1_l, *bW2_h, *bW2_l, *bWqkv_h, *bWqkv_l, *bW3_h, *bW3_l;
    bf16 *bWa1_h, *bWa1_l, *bWa2_h, *bWa2_l, *bWm_h, *bWm_l;
    cudaGetSymbolAddress((void**)&bHcat_h, g_bHcat_h);  cudaGetSymbolAddress((void**)&bHcat_l, g_bHcat_l);
    cudaGetSymbolAddress((void**)&bh_h,    g_bh_h);     cudaGetSymbolAddress((void**)&bh_l,    g_bh_l);
    cudaGetSymbolAddress((void**)&bHs_h,   g_bHs_h);    cudaGetSymbolAddress((void**)&bHs_l,   g_bHs_l);
    cudaGetSymbolAddress((void**)&bHp1_h,  g_bHp1_h);   cudaGetSymbolAddress((void**)&bHp1_l,  g_bHp1_l);
    cudaGetSymbolAddress((void**)&bXo_h,   g_bXo_h);    cudaGetSymbolAddress((void**)&bXo_l,   g_bXo_l);
    cudaGetSymbolAddress((void**)&bhall_h, g_bhall_h);  cudaGetSymbolAddress((void**)&bhall_l, g_bhall_l);
    cudaGetSymbolAddress((void**)&ba1_h,   g_ba1_h);    cudaGetSymbolAddress((void**)&ba1_l,   g_ba1_l);
    cudaGetSymbolAddress((void**)&bW1_h,   g_bW1_h);    cudaGetSymbolAddress((void**)&bW1_l,   g_bW1_l);
    cudaGetSymbolAddress((void**)&bW2_h,   g_bW2_h);    cudaGetSymbolAddress((void**)&bW2_l,   g_bW2_l);
    cudaGetSymbolAddress((void**)&bWqkv_h, g_bWqkv_h);  cudaGetSymbolAddress((void**)&bWqkv_l, g_bWqkv_l);
    cudaGetSymbolAddress((void**)&bW3_h,   g_bW3_h);    cudaGetSymbolAddress((void**)&bW3_l,   g_bW3_l);
    cudaGetSymbolAddress((void**)&bWa1_h,  g_bWa1_h);   cudaGetSymbolAddress((void**)&bWa1_l,  g_bWa1_l);
    cudaGetSymbolAddress((void**)&bWa2_h,  g_bWa2_h);   cudaGetSymbolAddress((void**)&bWa2_l,  g_bWa2_l);
    cudaGetSymbolAddress((void**)&bWm_h,   g_bWm_h);    cudaGetSymbolAddress((void**)&bWm_l,   g_bWm_l);

    // ---- prep ----
    build_hcat_kernel<<<(BNH * 1200 + 255) / 256, 256>>>(h, Hcat);
    transpose400_kernel<<<(400 * 400 + 255) / 256, 256>>>(Wo, WoT);
    tc_kernel<<<2, 256>>>(b1, bo, b3, W3, tc);

    // ---- weight + input conversions ----
    conv(h,    bh_h,    bh_l,    BNH * 400);
    conv(W1,   bW1_h,   bW1_l,   400 * 1600);
    conv(W2,   bW2_h,   bW2_l,   400 * 800);
    conv(Wqkv, bWqkv_h, bWqkv_l, 1200 * 400);
    conv(W3,   bW3_h,   bW3_l,   400 * 800);
    conv(Wa1,  bWa1_h,  bWa1_l,  400 * 800);
    conv(Wa2,  bWa2_h,  bWa2_l,  200 * 400);
    conv(Hcat, bHcat_h, bHcat_l, BNH * 1200);

    // ---- tensor-core GEMMs (history side) ----
    // Hp1 = Hcat @ W1[:, :1200]^T
    gemm_mma<0><<<dim3(4, 25), 256>>>(bHcat_h, bHcat_l, 1200, bW1_h, bW1_l, 1600,
                                      Hp1, 400, BNH, 400, 1200, nullptr, nullptr, nullptr);
    conv(Hp1, bHp1_h, bHp1_l, BNH * 400);
    // T1 = Hp1 @ W3[:, :400]^T
    gemm_mma<0><<<dim3(4, 25), 256>>>(bHp1_h, bHp1_l, 400, bW3_h, bW3_l, 800,
                                      T1, 400, BNH, 400, 400, nullptr, nullptr, nullptr);
    // Hs = h @ W2[:, 400:800]^T
    gemm_mma<0><<<dim3(4, 25), 256>>>(bh_h, bh_l, 400, bW2_h + 400, bW2_l + 400, 800,
                                      Hs, 400, BNH, 400, 400, nullptr, nullptr, nullptr);
    conv(Hs, bHs_h, bHs_l, BNH * 400);
    // Hq3 = Hs @ Wqkv^T
    gemm_mma<0><<<dim3(10, 25), 256>>>(bHs_h, bHs_l, 400, bWqkv_h, bWqkv_l, 400,
                                       Hq3, 1200, BNH, 1200, 400, nullptr, nullptr, nullptr);

    // ---- scalar small GEMMs (context side, LL=640 rows) ----
    gemm_abt<0><<<ggrid(LL, 400),  256>>>(c, 400, W1 + 1200, 1600, Cc, 400, LL, 400, 400, nullptr);
    gemm_abt<1><<<ggrid(LL, 400),  256>>>(c, 400, W2, 800, Cs, 400, LL, 400, 400, b2);
    gemm_abt<1><<<ggrid(LL, 1200), 256>>>(Cs, 400, Wqkv, 400, Cq3, 1200, LL, 1200, 400, bqkv);
    gemm_abt<0><<<ggrid(400, 400), 256>>>(W3 + 400, 800, WoT, 400, Wm, 400, 400, 400, 400, nullptr);
    conv(Wm, bWm_h, bWm_l, 400 * 400);
    gemm_abt<0><<<ggrid(LL, 400),  256>>>(Cc, 400, W3, 800, T2, 400, LL, 400, 400, nullptr);
    gemm_abt<1><<<ggrid(LL, 400),  256>>>(c, 400, Wa1 + 400, 800, CA, 400, LL, 400, 400, ba1);

    // ---- attention ----
    attn_kernel<<<NH_ * NHEAD, 640>>>(Cq3, Hq3, Xo);
    conv(Xo, bXo_h, bXo_l, MM * 400);

    // ---- tensor-core big GEMMs ----
    // hall = Xo @ Wm^T + T1 + T2 + tc
    gemm_mma<3><<<dim3(4, 250), 256>>>(bXo_h, bXo_l, 400, bWm_h, bWm_l, 400,
                                       hall, 400, MM, 400, 400, T1, T2, tc);
    conv(hall, bhall_h, bhall_l, MM * 400);
    // a1 = tanh(hall @ Wa1[:, :400]^T + CA)
    gemm_mma<4><<<dim3(4, 250), 256>>>(bhall_h, bhall_l, 400, bWa1_h, bWa1_l, 800,
                                       a1, 400, MM, 400, 400, CA, nullptr, nullptr);
    conv(a1, ba1_h, ba1_l, MM * 400);
    // a2 = tanh(a1 @ Wa2^T + ba2)
    gemm_mma<2><<<dim3(2, 250), 256>>>(ba1_h, ba1_l, 400, bWa2_h, bWa2_l, 400,
                                       a2, 200, MM, 200, 400, ba2, nullptr, nullptr);

    // ---- scoring + softmax + weighted sum ----
    score_kernel<<<MM / 8, dim3(32, 8)>>>(a2, Wa3, ba3, sc);
    softmax_u_kernel<<<LL, 128>>>(sc, hall, u);
}

// round 5
// speedup vs baseline: 2.0185x; 1.3048x over previous
#include <cuda_runtime.h>
#include <cuda_bf16.h>
#include <math.h>
#include <stdint.h>

// Problem constants
#define DD    400
#define BB    64
#define NC_   10
#define NH_   50
#define NHEAD 20
#define DH    20
#define LL    640      // BB*NC_
#define MM    32000    // BB*NC_*NH_
#define BNH   3200     // BB*NH_

typedef __nv_bfloat16 bf16;

// ---------------- fp32 device scratch ----------------
__device__ float g_Hcat[BNH * 1200];
__device__ float g_Hq3 [BNH * 1200];
__device__ float g_Cq3 [LL * 1200];
__device__ float g_WoT [400 * 400];
__device__ float g_T1  [BNH * 400];
__device__ float g_T2  [LL * 400];
__device__ float g_tc  [400];
__device__ float g_CA  [LL * 400];
__device__ float g_hall[MM * 400];
__device__ float g_a2  [MM * 200];
__device__ float g_s   [MM];

// ---------------- bf16 split scratch (hi/lo pairs) ----------------
__device__ __align__(16) bf16 g_bHcat_h[BNH * 1200], g_bHcat_l[BNH * 1200];
__device__ __align__(16) bf16 g_bh_h  [BNH * 400],  g_bh_l  [BNH * 400];
__device__ __align__(16) bf16 g_bHs_h [BNH * 400],  g_bHs_l [BNH * 400];
__device__ __align__(16) bf16 g_bHp1_h[BNH * 400],  g_bHp1_l[BNH * 400];
__device__ __align__(16) bf16 g_bc_h  [LL * 400],   g_bc_l  [LL * 400];
__device__ __align__(16) bf16 g_bCc_h [LL * 400],   g_bCc_l [LL * 400];
__device__ __align__(16) bf16 g_bCs_h [LL * 400],   g_bCs_l [LL * 400];
__device__ __align__(16) bf16 g_bXo_h [MM * 400],   g_bXo_l [MM * 400];
__device__ __align__(16) bf16 g_bhall_h[MM * 400],  g_bhall_l[MM * 400];
__device__ __align__(16) bf16 g_ba1_h [MM * 400],   g_ba1_l [MM * 400];
__device__ __align__(16) bf16 g_bW1_h [400 * 1600], g_bW1_l [400 * 1600];
__device__ __align__(16) bf16 g_bW2_h [400 * 800],  g_bW2_l [400 * 800];
__device__ __align__(16) bf16 g_bWqkv_h[1200 * 400],g_bWqkv_l[1200 * 400];
__device__ __align__(16) bf16 g_bW3_h [400 * 800],  g_bW3_l [400 * 800];
__device__ __align__(16) bf16 g_bWa1_h[400 * 800],  g_bWa1_l[400 * 800];
__device__ __align__(16) bf16 g_bWa2_h[200 * 400],  g_bWa2_l[200 * 400];
__device__ __align__(16) bf16 g_bWoT_h[400 * 400],  g_bWoT_l[400 * 400];
__device__ __align__(16) bf16 g_bWm_h [400 * 400],  g_bWm_l [400 * 400];

// ---------------- helpers ----------------
__device__ __forceinline__ uint32_t s2u(const void* p) {
    return (uint32_t)__cvta_generic_to_shared(p);
}
__device__ __forceinline__ void ldm4(uint32_t& r0, uint32_t& r1, uint32_t& r2, uint32_t& r3,
                                     uint32_t addr) {
    asm volatile("ldmatrix.sync.aligned.m8n8.x4.shared.b16 {%0,%1,%2,%3}, [%4];"
                 : "=r"(r0), "=r"(r1), "=r"(r2), "=r"(r3) : "r"(addr));
}
__device__ __forceinline__ void ldm2(uint32_t& r0, uint32_t& r1, uint32_t addr) {
    asm volatile("ldmatrix.sync.aligned.m8n8.x2.shared.b16 {%0,%1}, [%2];"
                 : "=r"(r0), "=r"(r1) : "r"(addr));
}
__device__ __forceinline__ void mma16816(float* d, const uint32_t* a, uint32_t b0, uint32_t b1) {
    asm volatile("mma.sync.aligned.m16n8k16.row.col.f32.bf16.bf16.f32 "
                 "{%0,%1,%2,%3}, {%4,%5,%6,%7}, {%8,%9}, {%0,%1,%2,%3};"
                 : "+f"(d[0]), "+f"(d[1]), "+f"(d[2]), "+f"(d[3])
                 : "r"(a[0]), "r"(a[1]), "r"(a[2]), "r"(a[3]), "r"(b0), "r"(b1));
}
__device__ __forceinline__ uint32_t pkbf(float a, float b) {
    __nv_bfloat162 t = __floats2bfloat162_rn(a, b);
    return *reinterpret_cast<uint32_t*>(&t);
}
__device__ __forceinline__ uint32_t pk2h(bf16 a, bf16 b) {
    __nv_bfloat162 t; t.x = a; t.y = b;
    return *reinterpret_cast<uint32_t*>(&t);
}

// ---------------- small prep kernels ----------------
__global__ void build_hcat_kernel(const float* __restrict__ h, float* __restrict__ out) {
    int idx = blockIdx.x * blockDim.x + threadIdx.x;
    if (idx >= BNH * 1200) return;
    int row = idx / 1200, col = idx % 1200;
    int b = row / NH_, j = row % NH_;
    int part = col / 400, d = col % 400;
    int jj = (part == 0) ? (j + NH_ - 1) % NH_ : ((part == 1) ? j : (j + 1) % NH_);
    out[idx] = h[(b * NH_ + jj) * 400 + d];
}

__global__ void transpose400_kernel(const float* __restrict__ Wo, float* __restrict__ WoT) {
    int idx = blockIdx.x * blockDim.x + threadIdx.x;
    if (idx >= 400 * 400) return;
    int r = idx / 400, c = idx % 400;
    WoT[idx] = Wo[c * 400 + r];
}

__global__ void tc_kernel(const float* __restrict__ b1, const float* __restrict__ bo,
                          const float* __restrict__ b3, const float* __restrict__ W3,
                          float* __restrict__ tc) {
    int r = blockIdx.x * blockDim.x + threadIdx.x;
    if (r >= 400) return;
    float acc = b3[r];
    for (int d = 0; d < 400; d++)
        acc += b1[d] * W3[r * 800 + d] + bo[d] * W3[r * 800 + 400 + d];
    tc[r] = acc;
}

__global__ void convert_split_kernel(const float* __restrict__ x,
                                     bf16* __restrict__ hi, bf16* __restrict__ lo, int n) {
    int i = blockIdx.x * blockDim.x + threadIdx.x;
    if (i >= n) return;
    float v = x[i];
    bf16 hh = __float2bfloat16_rn(v);
    hi[i] = hh;
    lo[i] = __float2bfloat16_rn(v - __bfloat162float(hh));
}

// ---------------- tensor-core GEMM (bf16 2-way split, 3 MMAs) ----------------
// C(MxN) = (Ah+Al)(MxK) @ (Bh+Bl)(NxK)^T + epilogue
// MODE 0: none | 1: +aux0[col] | 2: tanh(x+aux0[col])
// MODE 3: +aux0[(b,j)*N+col]+aux1[(b,i)*N+col]+aux2[col] | 4: tanh(x+aux0[(b,i)*N+col])
// OUT bit0: write fp32 C; bit1: write bf16 split Ch/Cl. N must be even.
#define TBM 128
#define TBN 128
#define TBK 16
#define SSTR 24

template <int MODE, int OUT>
__global__ __launch_bounds__(256) void gemm_mma(
    const bf16* __restrict__ Ah, const bf16* __restrict__ Al, int lda,
    const bf16* __restrict__ Bh, const bf16* __restrict__ Bl, int ldb,
    float* __restrict__ C, bf16* __restrict__ Ch, bf16* __restrict__ Cl,
    int ldc, int M, int N, int K,
    const float* __restrict__ aux0, const float* __restrict__ aux1,
    const float* __restrict__ aux2)
{
    __shared__ __align__(16) bf16 sAh[2][TBM * SSTR];
    __shared__ __align__(16) bf16 sAl[2][TBM * SSTR];
    __shared__ __align__(16) bf16 sBh[2][TBM * SSTR];
    __shared__ __align__(16) bf16 sBl[2][TBM * SSTR];

    const int tid = threadIdx.x;
    const int lrow = tid >> 1, lhalf = tid & 1;
    const int row0 = blockIdx.y * TBM, col0 = blockIdx.x * TBN;

    const bool aok = (row0 + lrow) < M;
    const bool bok = (col0 + lrow) < N;
    const int arow = aok ? (row0 + lrow) : 0;
    const int brow = bok ? (col0 + lrow) : 0;
    const bf16* Aph = Ah + (size_t)arow * lda + lhalf * 8;
    const bf16* Apl = Al + (size_t)arow * lda + lhalf * 8;
    const bf16* Bph = Bh + (size_t)brow * ldb + lhalf * 8;
    const bf16* Bpl = Bl + (size_t)brow * ldb + lhalf * 8;
    const int sidx = lrow * SSTR + lhalf * 8;

    const int w = tid >> 5, lane = tid & 31;
    const int wm = w >> 2, wn = w & 3;
    const int mrow = ((lane >> 3) & 1) * 8 + (lane & 7);
    const int koff = (lane >> 4) * 8;

    uint32_t aoff[4], boff[2];
    #pragma unroll
    for (int fm = 0; fm < 4; fm++)
        aoff[fm] = (uint32_t)(((wm * 64 + fm * 16 + mrow) * SSTR + koff) * 2);
    #pragma unroll
    for (int f = 0; f < 2; f++)
        boff[f] = (uint32_t)(((wn * 32 + f * 16 + mrow) * SSTR + koff) * 2);

    const uint32_t bAh = s2u(sAh), bAl = s2u(sAl), bBh = s2u(sBh), bBl = s2u(sBl);
    const uint32_t STB = TBM * SSTR * 2;

    float acc[4][4][4];
    #pragma unroll
    for (int i = 0; i < 4; i++)
        #pragma unroll
        for (int j = 0; j < 4; j++)
            #pragma unroll
            for (int e = 0; e < 4; e++) acc[i][j][e] = 0.f;

    const uint4 z4 = make_uint4(0u, 0u, 0u, 0u);
    {
        uint4 vah = aok ? *reinterpret_cast<const uint4*>(Aph) : z4;
        uint4 val = aok ? *reinterpret_cast<const uint4*>(Apl) : z4;
        uint4 vbh = bok ? *reinterpret_cast<const uint4*>(Bph) : z4;
        uint4 vbl = bok ? *reinterpret_cast<const uint4*>(Bpl) : z4;
        *reinterpret_cast<uint4*>(&sAh[0][sidx]) = vah;
        *reinterpret_cast<uint4*>(&sAl[0][sidx]) = val;
        *reinterpret_cast<uint4*>(&sBh[0][sidx]) = vbh;
        *reinterpret_cast<uint4*>(&sBl[0][sidx]) = vbl;
    }
    __syncthreads();

    const int nk = K / TBK;
    for (int t = 0; t < nk; t++) {
        const int st = t & 1;
        uint4 vah, val, vbh, vbl;
        if (t + 1 < nk) {
            const int k = (t + 1) * TBK;
            vah = aok ? *reinterpret_cast<const uint4*>(Aph + k) : z4;
            val = aok ? *reinterpret_cast<const uint4*>(Apl + k) : z4;
            vbh = bok ? *reinterpret_cast<const uint4*>(Bph + k) : z4;
            vbl = bok ? *reinterpret_cast<const uint4*>(Bpl + k) : z4;
        }

        uint32_t ah[4][4], al[4][4], bh[2][4], bl[2][4];
        #pragma unroll
        for (int fm = 0; fm < 4; fm++) {
            ldm4(ah[fm][0], ah[fm][1], ah[fm][2], ah[fm][3], bAh + st * STB + aoff[fm]);
            ldm4(al[fm][0], al[fm][1], al[fm][2], al[fm][3], bAl + st * STB + aoff[fm]);
        }
        #pragma unroll
        for (int f = 0; f < 2; f++) {
            ldm4(bh[f][0], bh[f][1], bh[f][2], bh[f][3], bBh + st * STB + boff[f]);
            ldm4(bl[f][0], bl[f][1], bl[f][2], bl[f][3], bBl + st * STB + boff[f]);
        }

        #pragma unroll
        for (int fm = 0; fm < 4; fm++) {
            #pragma unroll
            for (int f = 0; f < 2; f++) {
                mma16816(acc[fm][f * 2 + 0], ah[fm], bh[f][0], bh[f][2]);
                mma16816(acc[fm][f * 2 + 0], ah[fm], bl[f][0], bl[f][2]);
                mma16816(acc[fm][f * 2 + 0], al[fm], bh[f][0], bh[f][2]);
                mma16816(acc[fm][f * 2 + 1], ah[fm], bh[f][1], bh[f][3]);
                mma16816(acc[fm][f * 2 + 1], ah[fm], bl[f][1], bl[f][3]);
                mma16816(acc[fm][f * 2 + 1], al[fm], bh[f][1], bh[f][3]);
            }
        }

        if (t + 1 < nk) {
            const int ns = st ^ 1;
            *reinterpret_cast<uint4*>(&sAh[ns][sidx]) = vah;
            *reinterpret_cast<uint4*>(&sAl[ns][sidx]) = val;
            *reinterpret_cast<uint4*>(&sBh[ns][sidx]) = vbh;
            *reinterpret_cast<uint4*>(&sBl[ns][sidx]) = vbl;
            __syncthreads();
        }
    }

    // epilogue (pairwise: cols cc, cc+1)
    #pragma unroll
    for (int fm = 0; fm < 4; fm++) {
        #pragma unroll
        for (int half = 0; half < 2; half++) {
            const int r = row0 + wm * 64 + fm * 16 + (lane >> 2) + half * 8;
            if (r >= M) continue;
            int bb = 0, ii = 0, jj = 0;
            if (MODE == 3 || MODE == 4) { bb = r / 500; ii = (r / 50) % 10; jj = r % 50; }
            #pragma unroll
            for (int fn = 0; fn < 4; fn++) {
                const int cc = col0 + wn * 32 + fn * 8 + (lane & 3) * 2;
                if (cc >= N) continue;
                float v0 = acc[fm][fn][half * 2], v1 = acc[fm][fn][half * 2 + 1];
                if (MODE == 1) { v0 += aux0[cc]; v1 += aux0[cc + 1]; }
                if (MODE == 2) { v0 = tanhf(v0 + aux0[cc]); v1 = tanhf(v1 + aux0[cc + 1]); }
                if (MODE == 3) {
                    const float* p0 = aux0 + (size_t)(bb * 50 + jj) * N;
                    const float* p1 = aux1 + (size_t)(bb * 10 + ii) * N;
                    v0 += p0[cc] + p1[cc] + aux2[cc];
                    v1 += p0[cc + 1] + p1[cc + 1] + aux2[cc + 1];
                }
                if (MODE == 4) {
                    const float* p0 = aux0 + (size_t)(bb * 10 + ii) * N;
                    v0 = tanhf(v0 + p0[cc]); v1 = tanhf(v1 + p0[cc + 1]);
                }
                if (OUT & 1)
                    *reinterpret_cast<float2*>(&C[(size_t)r * ldc + cc]) = make_float2(v0, v1);
                if (OUT & 2) {
                    bf16 h0 = __float2bfloat16_rn(v0), h1 = __float2bfloat16_rn(v1);
                    *reinterpret_cast<uint32_t*>(&Ch[(size_t)r * ldc + cc]) = pk2h(h0, h1);
                    *reinterpret_cast<uint32_t*>(&Cl[(size_t)r * ldc + cc]) =
                        pkbf(v0 - __bfloat162float(h0), v1 - __bfloat162float(h1));
                }
            }
        }
    }
}

// ---------------- tensor-core flash attention ----------------
// grid (5 qtiles, 50 n, 20 h), 256 threads (8 warps, warp = 16 query rows)
// Q/K/V assembled as bf16 hi/lo splits; S via 3-MMA split; P split in-register;
// PV with V transposed in smem. Output written directly as bf16 split (Xo).
__global__ __launch_bounds__(256) void attn_mma(
    const float* __restrict__ Cq3, const float* __restrict__ Hq3,
    bf16* __restrict__ Xoh, bf16* __restrict__ Xol)
{
    __shared__ __align__(16) bf16 sm[18944];
    bf16* QH = sm;               // [128][40]
    bf16* QL = sm + 5120;
    bf16* KH = sm;               // reuse after Q frags loaded
    bf16* KL = sm + 5120;
    bf16* VTH = sm + 10240;      // [32][136]
    bf16* VTL = sm + 14592;

    const int qt = blockIdx.x, n = blockIdx.y, h = blockIdx.z;
    const int tid = threadIdx.x, w = tid >> 5, lane = tid & 31;
    const float scale = 0.22360679774997896f;  // 1/sqrt(20)
    const bf16 zb = __float2bfloat16_rn(0.f);

    // Phase 1: build Q tile (rows qt*128.., dims 0-19, pad 20-31 zero)
    for (int idx = tid; idx < 128 * 32; idx += 256) {
        int r = idx >> 5, d = idx & 31;
        float v = 0.f;
        if (d < 20) {
            int l = qt * 128 + r;
            int qr = (l / NC_) * NH_ + n;
            v = (Cq3[l * 1200 + h * 20 + d] + Hq3[qr * 1200 + h * 20 + d]) * scale;
        }
        bf16 hh = __float2bfloat16_rn(v);
        QH[r * 40 + d] = hh;
        QL[r * 40 + d] = __float2bfloat16_rn(v - __bfloat162float(hh));
    }
    __syncthreads();

    const int mrow = ((lane >> 3) & 1) * 8 + (lane & 7);
    const int koff = (lane >> 4) * 8;

    uint32_t qh[2][4], ql[2][4];
    #pragma unroll
    for (int kc = 0; kc < 2; kc++) {
        uint32_t a = (uint32_t)(((w * 16 + mrow) * 40 + kc * 16 + koff) * 2);
        ldm4(qh[kc][0], qh[kc][1], qh[kc][2], qh[kc][3], s2u(QH) + a);
        ldm4(ql[kc][0], ql[kc][1], ql[kc][2], ql[kc][3], s2u(QL) + a);
    }
    __syncthreads();

    // zero static pads: K dims 20-31, Vt dims 20-31
    for (int idx = tid; idx < 128 * 12; idx += 256) {
        int r = idx / 12, d = 20 + idx % 12;
        KH[r * 40 + d] = zb; KL[r * 40 + d] = zb;
    }
    for (int idx = tid; idx < 12 * 136; idx += 256) {
        int d = 20 + idx / 136, k = idx % 136;
        VTH[d * 136 + k] = zb; VTL[d * 136 + k] = zb;
    }

    float O0[3][4];
    #pragma unroll
    for (int f = 0; f < 3; f++)
        #pragma unroll
        for (int e = 0; e < 4; e++) O0[f][e] = 0.f;
    float zl = 0.f, zh2 = 0.f;

    for (int kt = 0; kt < 5; kt++) {
        __syncthreads();
        // build K [128][40] and Vt [32][136] (split)
        for (int idx = tid; idx < 128 * 20; idx += 256) {
            int kk = idx / 20, d = idx % 20;
            int m = kt * 128 + kk;
            int hr2 = (m / NC_) * NH_ + n;
            float kv = Cq3[m * 1200 + 400 + h * 20 + d] + Hq3[hr2 * 1200 + 400 + h * 20 + d];
            float vv = Cq3[m * 1200 + 800 + h * 20 + d] + Hq3[hr2 * 1200 + 800 + h * 20 + d];
            bf16 kh_ = __float2bfloat16_rn(kv);
            KH[kk * 40 + d] = kh_;
            KL[kk * 40 + d] = __float2bfloat16_rn(kv - __bfloat162float(kh_));
            bf16 vh_ = __float2bfloat16_rn(vv);
            VTH[d * 136 + kk] = vh_;
            VTL[d * 136 + kk] = __float2bfloat16_rn(vv - __bfloat162float(vh_));
        }
        __syncthreads();

        // S = Q K^T  (16 n8 frags x 4 fp32)
        union { float f[16][4]; uint32_t u[16][4]; } SP;
        #pragma unroll
        for (int f = 0; f < 16; f++)
            #pragma unroll
            for (int e = 0; e < 4; e++) SP.f[f][e] = 0.f;

        #pragma unroll
        for (int g = 0; g < 8; g++) {
            uint32_t kh[2][4], kl[2][4];
            #pragma unroll
            for (int kc = 0; kc < 2; kc++) {
                uint32_t a = (uint32_t)(((g * 16 + mrow) * 40 + kc * 16 + koff) * 2);
                ldm4(kh[kc][0], kh[kc][1], kh[kc][2], kh[kc][3], s2u(KH) + a);
                ldm4(kl[kc][0], kl[kc][1], kl[kc][2], kl[kc][3], s2u(KL) + a);
            }
            #pragma unroll
            for (int kc = 0; kc < 2; kc++) {
                mma16816(SP.f[2 * g + 0], qh[kc], kh[kc][0], kh[kc][2]);
                mma16816(SP.f[2 * g + 0], qh[kc], kl[kc][0], kl[kc][2]);
                mma16816(SP.f[2 * g + 0], ql[kc], kh[kc][0], kh[kc][2]);
                mma16816(SP.f[2 * g + 1], qh[kc], kh[kc][1], kh[kc][3]);
                mma16816(SP.f[2 * g + 1], qh[kc], kl[kc][1], kl[kc][3]);
                mma16816(SP.f[2 * g + 1], ql[kc], kh[kc][1], kh[kc][3]);
            }
        }

        // exp + split P (in place)
        #pragma unroll
        for (int f = 0; f < 16; f++) {
            float e0 = __expf(SP.f[f][0]), e1 = __expf(SP.f[f][1]);
            float e2 = __expf(SP.f[f][2]), e3 = __expf(SP.f[f][3]);
            zl += e0 + e1; zh2 += e2 + e3;
            bf16 h0 = __float2bfloat16_rn(e0), h1 = __float2bfloat16_rn(e1);
            bf16 h2 = __float2bfloat16_rn(e2), h3 = __float2bfloat16_rn(e3);
            uint32_t ph01 = pk2h(h0, h1), ph23 = pk2h(h2, h3);
            uint32_t pl01 = pkbf(e0 - __bfloat162float(h0), e1 - __bfloat162float(h1));
            uint32_t pl23 = pkbf(e2 - __bfloat162float(h2), e3 - __bfloat162float(h3));
            SP.u[f][0] = ph01; SP.u[f][1] = ph23; SP.u[f][2] = pl01; SP.u[f][3] = pl23;
        }

        // O += P V   (V: dims as n, keys as k)
        #pragma unroll
        for (int kc2 = 0; kc2 < 8; kc2++) {
            uint32_t ah[4] = { SP.u[2 * kc2][0], SP.u[2 * kc2][1],
                               SP.u[2 * kc2 + 1][0], SP.u[2 * kc2 + 1][1] };
            uint32_t al[4] = { SP.u[2 * kc2][2], SP.u[2 * kc2][3],
                               SP.u[2 * kc2 + 1][2], SP.u[2 * kc2 + 1][3] };
            uint32_t vh4[4], vl4[4], vh2[2], vl2[2];
            uint32_t a4 = (uint32_t)((mrow * 136 + kc2 * 16 + koff) * 2);
            uint32_t a2 = (uint32_t)(((16 + (lane & 7)) * 136 + kc2 * 16 + ((lane >> 3) & 1) * 8) * 2);
            ldm4(vh4[0], vh4[1], vh4[2], vh4[3], s2u(VTH) + a4);
            ldm4(vl4[0], vl4[1], vl4[2], vl4[3], s2u(VTL) + a4);
            ldm2(vh2[0], vh2[1], s2u(VTH) + a2);
            ldm2(vl2[0], vl2[1], s2u(VTL) + a2);
            mma16816(O0[0], ah, vh4[0], vh4[2]);
            mma16816(O0[0], ah, vl4[0], vl4[2]);
            mma16816(O0[0], al, vh4[0], vh4[2]);
            mma16816(O0[1], ah, vh4[1], vh4[3]);
            mma16816(O0[1], ah, vl4[1], vl4[3]);
            mma16816(O0[1], al, vh4[1], vh4[3]);
            mma16816(O0[2], ah, vh2[0], vh2[1]);
            mma16816(O0[2], ah, vl2[0], vl2[1]);
            mma16816(O0[2], al, vh2[0], vh2[1]);
        }
    }

    // Z reduction within quads (lanes sharing the same row)
    zl  += __shfl_xor_sync(0xffffffffu, zl, 1);
    zl  += __shfl_xor_sync(0xffffffffu, zl, 2);
    zh2 += __shfl_xor_sync(0xffffffffu, zh2, 1);
    zh2 += __shfl_xor_sync(0xffffffffu, zh2, 2);
    float izl = 1.f / zl, izh = 1.f / zh2;

    // store O (bf16 split) -> Xo[(l*50+n)*400 + h*20 + d]
    const int rowq = lane >> 2;
    #pragma unroll
    for (int f = 0; f < 3; f++) {
        int d0 = f * 8 + (lane & 3) * 2;
        if (d0 >= 20) continue;
        #pragma unroll
        for (int half = 0; half < 2; half++) {
            int lq = qt * 128 + w * 16 + rowq + half * 8;
            float v0 = O0[f][half * 2]     * (half ? izh : izl);
            float v1 = O0[f][half * 2 + 1] * (half ? izh : izl);
            size_t o = (size_t)(lq * NH_ + n) * 400 + h * 20 + d0;
            bf16 h0 = __float2bfloat16_rn(v0), h1 = __float2bfloat16_rn(v1);
            *reinterpret_cast<uint32_t*>(&Xoh[o]) = pk2h(h0, h1);
            *reinterpret_cast<uint32_t*>(&Xol[o]) =
                pkbf(v0 - __bfloat162float(h0), v1 - __bfloat162float(h1));
        }
    }
}

// ---------------- score: s[m] = a2[m,:]·Wa3 + ba3 ----------------
__global__ void score_kernel(const float* __restrict__ a2, const float* __restrict__ Wa3,
                             const float* __restrict__ ba3, float* __restrict__ s)
{
    int row = blockIdx.x * 8 + threadIdx.y;
    if (row >= MM) return;
    int lane = threadIdx.x;
    float acc = 0.f;
    for (int d = lane; d < 200; d += 32) acc += a2[(size_t)row * 200 + d] * Wa3[d];
    #pragma unroll
    for (int o = 16; o > 0; o >>= 1) acc += __shfl_xor_sync(0xffffffffu, acc, o);
    if (lane == 0) s[row] = acc + ba3[0];
}

// ---------------- softmax over j + weighted sum -> u ----------------
__global__ void softmax_u_kernel(const float* __restrict__ s, const float* __restrict__ hall,
                                 float* __restrict__ u)
{
    __shared__ float a[NH_];
    int bi = blockIdx.x;
    if (threadIdx.x == 0) {
        float mx = -1e30f;
        for (int j = 0; j < NH_; j++) mx = fmaxf(mx, s[bi * NH_ + j]);
        float Z = 0.f;
        for (int j = 0; j < NH_; j++) { float e = __expf(s[bi * NH_ + j] - mx); a[j] = e; Z += e; }
        float iz = 1.f / Z;
        for (int j = 0; j < NH_; j++) a[j] *= iz;
    }
    __syncthreads();
    for (int d = threadIdx.x; d < 400; d += blockDim.x) {
        float acc = 0.f;
        for (int j = 0; j < NH_; j++)
            acc += a[j] * hall[((size_t)bi * NH_ + j) * 400 + d];
        u[(size_t)bi * 400 + d] = acc;
    }
}

// ---------------- launch ----------------
static inline dim3 mgrid(int M, int N) { return dim3((N + TBN - 1) / TBN, (M + TBM - 1) / TBM); }
static inline void conv(const float* x, bf16* hi, bf16* lo, int n) {
    convert_split_kernel<<<(n + 255) / 256, 256>>>(x, hi, lo, n);
}

extern "C" void kernel_launch(void* const* d_in, const int* in_sizes, int n_in,
                              void* d_out, int out_size)
{
    const float* h    = (const float*)d_in[0];
    const float* c    = (const float*)d_in[2];
    const float* W1   = (const float*)d_in[4];
    const float* b1   = (const float*)d_in[5];
    const float* W2   = (const float*)d_in[6];
    const float* b2   = (const float*)d_in[7];
    const float* W3   = (const float*)d_in[8];
    const float* b3   = (const float*)d_in[9];
    const float* Wa1  = (const float*)d_in[10];
    const float* ba1  = (const float*)d_in[11];
    const float* Wa2  = (const float*)d_in[12];
    const float* ba2  = (const float*)d_in[13];
    const float* Wa3  = (const float*)d_in[14];
    const float* ba3  = (const float*)d_in[15];
    const float* Wqkv = (const float*)d_in[16];
    const float* bqkv = (const float*)d_in[17];
    const float* Wo   = (const float*)d_in[18];
    const float* bo   = (const float*)d_in[19];
    float* u = (float*)d_out;

    float *Hcat, *Hq3, *Cq3, *WoT, *T1, *T2, *tc, *CA, *hall, *a2, *sc;
    cudaGetSymbolAddress((void**)&Hcat, g_Hcat);
    cudaGetSymbolAddress((void**)&Hq3,  g_Hq3);
    cudaGetSymbolAddress((void**)&Cq3,  g_Cq3);
    cudaGetSymbolAddress((void**)&WoT,  g_WoT);
    cudaGetSymbolAddress((void**)&T1,   g_T1);
    cudaGetSymbolAddress((void**)&T2,   g_T2);
    cudaGetSymbolAddress((void**)&tc,   g_tc);
    cudaGetSymbolAddress((void**)&CA,   g_CA);
    cudaGetSymbolAddress((void**)&hall, g_hall);
    cudaGetSymbolAddress((void**)&a2,   g_a2);
    cudaGetSymbolAddress((void**)&sc,   g_s);

    bf16 *bHcat_h, *bHcat_l, *bh_h, *bh_l, *bHs_h, *bHs_l, *bHp1_h, *bHp1_l;
    bf16 *bc_h, *bc_l, *bCc_h, *bCc_l, *bCs_h, *bCs_l;
    bf16 *bXo_h, *bXo_l, *bhall_h, *bhall_l, *ba1_h, *ba1_l;
    bf16 *bW1_h, *bW1_l, *bW2_h, *bW2_l, *bWqkv_h, *bWqkv_l, *bW3_h, *bW3_l;
    bf16 *bWa1_h, *bWa1_l, *bWa2_h, *bWa2_l, *bWoT_h, *bWoT_l, *bWm_h, *bWm_l;
    cudaGetSymbolAddress((void**)&bHcat_h, g_bHcat_h);  cudaGetSymbolAddress((void**)&bHcat_l, g_bHcat_l);
    cudaGetSymbolAddress((void**)&bh_h,    g_bh_h);     cudaGetSymbolAddress((void**)&bh_l,    g_bh_l);
    cudaGetSymbolAddress((void**)&bHs_h,   g_bHs_h);    cudaGetSymbolAddress((void**)&bHs_l,   g_bHs_l);
    cudaGetSymbolAddress((void**)&bHp1_h,  g_bHp1_h);   cudaGetSymbolAddress((void**)&bHp1_l,  g_bHp1_l);
    cudaGetSymbolAddress((void**)&bc_h,    g_bc_h);     cudaGetSymbolAddress((void**)&bc_l,    g_bc_l);
    cudaGetSymbolAddress((void**)&bCc_h,   g_bCc_h);    cudaGetSymbolAddress((void**)&bCc_l,   g_bCc_l);
    cudaGetSymbolAddress((void**)&bCs_h,   g_bCs_h);    cudaGetSymbolAddress((void**)&bCs_l,   g_bCs_l);
    cudaGetSymbolAddress((void**)&bXo_h,   g_bXo_h);    cudaGetSymbolAddress((void**)&bXo_l,   g_bXo_l);
    cudaGetSymbolAddress((void**)&bhall_h, g_bhall_h);  cudaGetSymbolAddress((void**)&bhall_l, g_bhall_l);
    cudaGetSymbolAddress((void**)&ba1_h,   g_ba1_h);    cudaGetSymbolAddress((void**)&ba1_l,   g_ba1_l);
    cudaGetSymbolAddress((void**)&bW1_h,   g_bW1_h);    cudaGetSymbolAddress((void**)&bW1_l,   g_bW1_l);
    cudaGetSymbolAddress((void**)&bW2_h,   g_bW2_h);    cudaGetSymbolAddress((void**)&bW2_l,   g_bW2_l);
    cudaGetSymbolAddress((void**)&bWqkv_h, g_bWqkv_h);  cudaGetSymbolAddress((void**)&bWqkv_l, g_bWqkv_l);
    cudaGetSymbolAddress((void**)&bW3_h,   g_bW3_h);    cudaGetSymbolAddress((void**)&bW3_l,   g_bW3_l);
    cudaGetSymbolAddress((void**)&bWa1_h,  g_bWa1_h);   cudaGetSymbolAddress((void**)&bWa1_l,  g_bWa1_l);
    cudaGetSymbolAddress((void**)&bWa2_h,  g_bWa2_h);   cudaGetSymbolAddress((void**)&bWa2_l,  g_bWa2_l);
    cudaGetSymbolAddress((void**)&bWoT_h,  g_bWoT_h);   cudaGetSymbolAddress((void**)&bWoT_l,  g_bWoT_l);
    cudaGetSymbolAddress((void**)&bWm_h,   g_bWm_h);    cudaGetSymbolAddress((void**)&bWm_l,   g_bWm_l);

    // ---- prep ----
    build_hcat_kernel<<<(BNH * 1200 + 255) / 256, 256>>>(h, Hcat);
    transpose400_kernel<<<(400 * 400 + 255) / 256, 256>>>(Wo, WoT);
    tc_kernel<<<2, 256>>>(b1, bo, b3, W3, tc);

    // ---- conversions (weights + primary inputs only) ----
    conv(h,    bh_h,    bh_l,    BNH * 400);
    conv(c,    bc_h,    bc_l,    LL * 400);
    conv(W1,   bW1_h,   bW1_l,   400 * 1600);
    conv(W2,   bW2_h,   bW2_l,   400 * 800);
    conv(Wqkv, bWqkv_h, bWqkv_l, 1200 * 400);
    conv(W3,   bW3_h,   bW3_l,   400 * 800);
    conv(Wa1,  bWa1_h,  bWa1_l,  400 * 800);
    conv(Wa2,  bWa2_h,  bWa2_l,  200 * 400);
    conv(Hcat, bHcat_h, bHcat_l, BNH * 1200);
    conv(WoT,  bWoT_h,  bWoT_l,  400 * 400);

    // ---- tensor-core GEMMs ----
    // Hp1 = Hcat @ W1a^T  (split out)
    gemm_mma<0, 2><<<mgrid(BNH, 400), 256>>>(bHcat_h, bHcat_l, 1200, bW1_h, bW1_l, 1600,
        nullptr, bHp1_h, bHp1_l, 400, BNH, 400, 1200, nullptr, nullptr, nullptr);
    // T1 = Hp1 @ W3a^T  (fp32)
    gemm_mma<0, 1><<<mgrid(BNH, 400), 256>>>(bHp1_h, bHp1_l, 400, bW3_h, bW3_l, 800,
        T1, nullptr, nullptr, 400, BNH, 400, 400, nullptr, nullptr, nullptr);
    // Hs = h @ W2b^T  (split)
    gemm_mma<0, 2><<<mgrid(BNH, 400), 256>>>(bh_h, bh_l, 400, bW2_h + 400, bW2_l + 400, 800,
        nullptr, bHs_h, bHs_l, 400, BNH, 400, 400, nullptr, nullptr, nullptr);
    // Hq3 = Hs @ Wqkv^T  (fp32)
    gemm_mma<0, 1><<<mgrid(BNH, 1200), 256>>>(bHs_h, bHs_l, 400, bWqkv_h, bWqkv_l, 400,
        Hq3, nullptr, nullptr, 1200, BNH, 1200, 400, nullptr, nullptr, nullptr);
    // Cc = c @ W1b^T  (split)
    gemm_mma<0, 2><<<mgrid(LL, 400), 256>>>(bc_h, bc_l, 400, bW1_h + 1200, bW1_l + 1200, 1600,
        nullptr, bCc_h, bCc_l, 400, LL, 400, 400, nullptr, nullptr, nullptr);
    // Cs = c @ W2a^T + b2  (split)
    gemm_mma<1, 2><<<mgrid(LL, 400), 256>>>(bc_h, bc_l, 400, bW2_h, bW2_l, 800,
        nullptr, bCs_h, bCs_l, 400, LL, 400, 400, b2, nullptr, nullptr);
    // Cq3 = Cs @ Wqkv^T + bqkv  (fp32)
    gemm_mma<1, 1><<<mgrid(LL, 1200), 256>>>(bCs_h, bCs_l, 400, bWqkv_h, bWqkv_l, 400,
        Cq3, nullptr, nullptr, 1200, LL, 1200, 400, bqkv, nullptr, nullptr);
    // T2 = Cc @ W3a^T  (fp32)
    gemm_mma<0, 1><<<mgrid(LL, 400), 256>>>(bCc_h, bCc_l, 400, bW3_h, bW3_l, 800,
        T2, nullptr, nullptr, 400, LL, 400, 400, nullptr, nullptr, nullptr);
    // CA = c @ Wa1b^T + ba1  (fp32)
    gemm_mma<1, 1><<<mgrid(LL, 400), 256>>>(bc_h, bc_l, 400, bWa1_h + 400, bWa1_l + 400, 800,
        CA, nullptr, nullptr, 400, LL, 400, 400, ba1, nullptr, nullptr);
    // Wm = W3b @ WoT^T  (split; M=400 guarded)
    gemm_mma<0, 2><<<mgrid(400, 400), 256>>>(bW3_h + 400, bW3_l + 400, 800, bWoT_h, bWoT_l, 400,
        nullptr, bWm_h, bWm_l, 400, 400, 400, 400, nullptr, nullptr, nullptr);

    // ---- attention (tensor-core flash) -> bXo split ----
    attn_mma<<<dim3(5, NH_, NHEAD), 256>>>(Cq3, Hq3, bXo_h, bXo_l);

    // ---- big GEMMs ----
    // hall = Xo @ Wm^T + T1 + T2 + tc  (fp32 + split)
    gemm_mma<3, 3><<<mgrid(MM, 400), 256>>>(bXo_h, bXo_l, 400, bWm_h, bWm_l, 400,
        hall, bhall_h, bhall_l, 400, MM, 400, 400, T1, T2, tc);
    // a1 = tanh(hall @ Wa1a^T + CA)  (split)
    gemm_mma<4, 2><<<mgrid(MM, 400), 256>>>(bhall_h, bhall_l, 400, bWa1_h, bWa1_l, 800,
        nullptr, ba1_h, ba1_l, 400, MM, 400, 400, CA, nullptr, nullptr);
    // a2 = tanh(a1 @ Wa2^T + ba2)  (fp32)
    gemm_mma<2, 1><<<mgrid(MM, 200), 256>>>(ba1_h, ba1_l, 400, bWa2_h, bWa2_l, 400,
        a2, nullptr, nullptr, 200, MM, 200, 400, ba2, nullptr, nullptr);

    // ---- scoring + softmax + weighted sum ----
    score_kernel<<<MM / 8, dim3(32, 8)>>>(a2, Wa3, ba3, sc);
    softmax_u_kernel<<<LL, 128>>>(sc, hall, u);
}

// round 6
// speedup vs baseline: 2.0342x; 1.0077x over previous
#include <cuda_runtime.h>
#include <cuda_bf16.h>
#include <math.h>
#include <stdint.h>

// Problem constants
#define DD    400
#define BB    64
#define NC_   10
#define NH_   50
#define NHEAD 20
#define DH    20
#define LL    640      // BB*NC_
#define MM    32000    // BB*NC_*NH_
#define BNH   3200     // BB*NH_

typedef __nv_bfloat16 bf16;

// ---------------- fp32 device scratch ----------------
__device__ float g_Hq3 [BNH * 1200];
__device__ float g_Cq3 [LL * 1200];
__device__ float g_T1  [BNH * 400];
__device__ float g_T2  [LL * 400];
__device__ float g_tc  [400];
__device__ float g_CA  [LL * 400];
__device__ float g_hall[MM * 400];
__device__ float g_a2  [MM * 200];
__device__ float g_s   [MM];

// ---------------- bf16 split scratch (hi/lo pairs) ----------------
__device__ __align__(16) bf16 g_bHcat_h[BNH * 1200], g_bHcat_l[BNH * 1200];
__device__ __align__(16) bf16 g_bh_h  [BNH * 400],  g_bh_l  [BNH * 400];
__device__ __align__(16) bf16 g_bHs_h [BNH * 400],  g_bHs_l [BNH * 400];
__device__ __align__(16) bf16 g_bHp1_h[BNH * 400],  g_bHp1_l[BNH * 400];
__device__ __align__(16) bf16 g_bc_h  [LL * 400],   g_bc_l  [LL * 400];
__device__ __align__(16) bf16 g_bCc_h [LL * 400],   g_bCc_l [LL * 400];
__device__ __align__(16) bf16 g_bCs_h [LL * 400],   g_bCs_l [LL * 400];
__device__ __align__(16) bf16 g_bXo_h [MM * 400],   g_bXo_l [MM * 400];
__device__ __align__(16) bf16 g_bhall_h[MM * 400],  g_bhall_l[MM * 400];
__device__ __align__(16) bf16 g_ba1_h [MM * 400],   g_ba1_l [MM * 400];
__device__ __align__(16) bf16 g_bW1_h [400 * 1600], g_bW1_l [400 * 1600];
__device__ __align__(16) bf16 g_bW2_h [400 * 800],  g_bW2_l [400 * 800];
__device__ __align__(16) bf16 g_bWqkv_h[1200 * 400],g_bWqkv_l[1200 * 400];
__device__ __align__(16) bf16 g_bW3_h [400 * 800],  g_bW3_l [400 * 800];
__device__ __align__(16) bf16 g_bWa1_h[400 * 800],  g_bWa1_l[400 * 800];
__device__ __align__(16) bf16 g_bWa2_h[200 * 400],  g_bWa2_l[200 * 400];
__device__ __align__(16) bf16 g_bWoT_h[400 * 400],  g_bWoT_l[400 * 400];
__device__ __align__(16) bf16 g_bWm_h [400 * 400],  g_bWm_l [400 * 400];

// attention pre-split K/V
// K: [n][h][m(640)][32 padded]   V: [n][h][d(20)][m(640)]
__device__ __align__(16) bf16 g_KHg[50 * 20 * 640 * 32], g_KLg[50 * 20 * 640 * 32];
__device__ __align__(16) bf16 g_VHg[50 * 20 * 20 * 640], g_VLg[50 * 20 * 20 * 640];

// ---------------- helpers ----------------
__device__ __forceinline__ uint32_t s2u(const void* p) {
    return (uint32_t)__cvta_generic_to_shared(p);
}
__device__ __forceinline__ void ldm4(uint32_t& r0, uint32_t& r1, uint32_t& r2, uint32_t& r3,
                                     uint32_t addr) {
    asm volatile("ldmatrix.sync.aligned.m8n8.x4.shared.b16 {%0,%1,%2,%3}, [%4];"
                 : "=r"(r0), "=r"(r1), "=r"(r2), "=r"(r3) : "r"(addr));
}
__device__ __forceinline__ void ldm2(uint32_t& r0, uint32_t& r1, uint32_t addr) {
    asm volatile("ldmatrix.sync.aligned.m8n8.x2.shared.b16 {%0,%1}, [%2];"
                 : "=r"(r0), "=r"(r1) : "r"(addr));
}
__device__ __forceinline__ void mma16816(float* d, const uint32_t* a, uint32_t b0, uint32_t b1) {
    asm volatile("mma.sync.aligned.m16n8k16.row.col.f32.bf16.bf16.f32 "
                 "{%0,%1,%2,%3}, {%4,%5,%6,%7}, {%8,%9}, {%0,%1,%2,%3};"
                 : "+f"(d[0]), "+f"(d[1]), "+f"(d[2]), "+f"(d[3])
                 : "r"(a[0]), "r"(a[1]), "r"(a[2]), "r"(a[3]), "r"(b0), "r"(b1));
}
__device__ __forceinline__ uint32_t pkbf(float a, float b) {
    __nv_bfloat162 t = __floats2bfloat162_rn(a, b);
    return *reinterpret_cast<uint32_t*>(&t);
}
__device__ __forceinline__ uint32_t pk2h(bf16 a, bf16 b) {
    __nv_bfloat162 t; t.x = a; t.y = b;
    return *reinterpret_cast<uint32_t*>(&t);
}

// ---------------- merged convert: 8 segments in one launch ----------------
struct ConvParams {
    const float* src[8];
    bf16* hi[8];
    bf16* lo[8];
    int cum[9];
};
__global__ void conv_all_kernel(ConvParams P) {
    int i = blockIdx.x * blockDim.x + threadIdx.x;
    if (i >= P.cum[8]) return;
    int g = 0;
    #pragma unroll
    for (int s = 1; s < 8; s++) if (i >= P.cum[s]) g = s;
    int local = i - P.cum[g];
    float v = P.src[g][local];
    bf16 hh = __float2bfloat16_rn(v);
    P.hi[g][local] = hh;
    P.lo[g][local] = __float2bfloat16_rn(v - __bfloat162float(hh));
}

// ---------------- Hcat gathered directly in bf16 (pairwise) ----------------
__global__ void build_hcat_bf16(const bf16* __restrict__ hh, const bf16* __restrict__ hl,
                                bf16* __restrict__ oh, bf16* __restrict__ ol) {
    int idx = blockIdx.x * blockDim.x + threadIdx.x;   // pairs
    if (idx >= BNH * 600) return;
    int row = idx / 600, pr = idx % 600;
    int col = pr * 2;
    int b = row / NH_, j = row % NH_;
    int part = col / 400, d = col % 400;
    int jj = (part == 0) ? (j + NH_ - 1) % NH_ : ((part == 1) ? j : (j + 1) % NH_);
    int s = (b * NH_ + jj) * 400 + d;
    reinterpret_cast<uint32_t*>(oh)[idx] = *reinterpret_cast<const uint32_t*>(&hh[s]);
    reinterpret_cast<uint32_t*>(ol)[idx] = *reinterpret_cast<const uint32_t*>(&hl[s]);
}

// ---------------- Wo transpose + split fused ----------------
__global__ void transpose_split_kernel(const float* __restrict__ Wo,
                                       bf16* __restrict__ th, bf16* __restrict__ tl) {
    int idx = blockIdx.x * blockDim.x + threadIdx.x;
    if (idx >= 400 * 400) return;
    int n = idx / 400, k = idx % 400;
    float v = Wo[k * 400 + n];
    bf16 hh = __float2bfloat16_rn(v);
    th[idx] = hh;
    tl[idx] = __float2bfloat16_rn(v - __bfloat162float(hh));
}

__global__ void tc_kernel(const float* __restrict__ b1, const float* __restrict__ bo,
                          const float* __restrict__ b3, const float* __restrict__ W3,
                          float* __restrict__ tc) {
    int r = blockIdx.x * blockDim.x + threadIdx.x;
    if (r >= 400) return;
    float acc = b3[r];
    for (int d = 0; d < 400; d++)
        acc += b1[d] * W3[r * 800 + d] + bo[d] * W3[r * 800 + 400 + d];
    tc[r] = acc;
}

// ---------------- shared tensor-core GEMM core (bf16 2-way split, 3 MMAs) ----------------
// C(MxN) = (Ah+Al)(MxK) @ (Bh+Bl)(NxK)^T + epilogue
// mode 0: none | 1: +aux0[col] | 2: tanh(x+aux0[col])
// mode 3: +aux0[(b,j)*N+col]+aux1[(b,i)*N+col]+aux2[col] | 4: tanh(x+aux0[(b,i)*N+col])
// out bit0: fp32 C; bit1: bf16 split Ch/Cl.
#define TBM 128
#define TBN 128
#define TBK 16
#define SSTR 24

__device__ __forceinline__ void gemm_core(
    const bf16* __restrict__ Ah, const bf16* __restrict__ Al, int lda,
    const bf16* __restrict__ Bh, const bf16* __restrict__ Bl, int ldb,
    float* __restrict__ C, bf16* __restrict__ Ch, bf16* __restrict__ Cl,
    int ldc, int M, int N, int K,
    const float* __restrict__ aux0, const float* __restrict__ aux1,
    const float* __restrict__ aux2,
    int row0, int col0, int mode, int out)
{
    __shared__ __align__(16) bf16 sAh[2][TBM * SSTR];
    __shared__ __align__(16) bf16 sAl[2][TBM * SSTR];
    __shared__ __align__(16) bf16 sBh[2][TBM * SSTR];
    __shared__ __align__(16) bf16 sBl[2][TBM * SSTR];

    const int tid = threadIdx.x;
    const int lrow = tid >> 1, lhalf = tid & 1;

    const bool aok = (row0 + lrow) < M;
    const bool bok = (col0 + lrow) < N;
    const int arow = aok ? (row0 + lrow) : 0;
    const int brow = bok ? (col0 + lrow) : 0;
    const bf16* Aph = Ah + (size_t)arow * lda + lhalf * 8;
    const bf16* Apl = Al + (size_t)arow * lda + lhalf * 8;
    const bf16* Bph = Bh + (size_t)brow * ldb + lhalf * 8;
    const bf16* Bpl = Bl + (size_t)brow * ldb + lhalf * 8;
    const int sidx = lrow * SSTR + lhalf * 8;

    const int w = tid >> 5, lane = tid & 31;
    const int wm = w >> 2, wn = w & 3;
    const int mrow = ((lane >> 3) & 1) * 8 + (lane & 7);
    const int koff = (lane >> 4) * 8;

    uint32_t aoff[4], boff[2];
    #pragma unroll
    for (int fm = 0; fm < 4; fm++)
        aoff[fm] = (uint32_t)(((wm * 64 + fm * 16 + mrow) * SSTR + koff) * 2);
    #pragma unroll
    for (int f = 0; f < 2; f++)
        boff[f] = (uint32_t)(((wn * 32 + f * 16 + mrow) * SSTR + koff) * 2);

    const uint32_t bAh = s2u(sAh), bAl = s2u(sAl), bBh = s2u(sBh), bBl = s2u(sBl);
    const uint32_t STB = TBM * SSTR * 2;

    float acc[4][4][4];
    #pragma unroll
    for (int i = 0; i < 4; i++)
        #pragma unroll
        for (int j = 0; j < 4; j++)
            #pragma unroll
            for (int e = 0; e < 4; e++) acc[i][j][e] = 0.f;

    const uint4 z4 = make_uint4(0u, 0u, 0u, 0u);
    {
        uint4 vah = aok ? *reinterpret_cast<const uint4*>(Aph) : z4;
        uint4 val = aok ? *reinterpret_cast<const uint4*>(Apl) : z4;
        uint4 vbh = bok ? *reinterpret_cast<const uint4*>(Bph) : z4;
        uint4 vbl = bok ? *reinterpret_cast<const uint4*>(Bpl) : z4;
        *reinterpret_cast<uint4*>(&sAh[0][sidx]) = vah;
        *reinterpret_cast<uint4*>(&sAl[0][sidx]) = val;
        *reinterpret_cast<uint4*>(&sBh[0][sidx]) = vbh;
        *reinterpret_cast<uint4*>(&sBl[0][sidx]) = vbl;
    }
    __syncthreads();

    const int nk = K / TBK;
    for (int t = 0; t < nk; t++) {
        const int st = t & 1;
        uint4 vah, val, vbh, vbl;
        if (t + 1 < nk) {
            const int k = (t + 1) * TBK;
            vah = aok ? *reinterpret_cast<const uint4*>(Aph + k) : z4;
            val = aok ? *reinterpret_cast<const uint4*>(Apl + k) : z4;
            vbh = bok ? *reinterpret_cast<const uint4*>(Bph + k) : z4;
            vbl = bok ? *reinterpret_cast<const uint4*>(Bpl + k) : z4;
        }

        uint32_t ah[4][4], al[4][4], bh[2][4], bl[2][4];
        #pragma unroll
        for (int fm = 0; fm < 4; fm++) {
            ldm4(ah[fm][0], ah[fm][1], ah[fm][2], ah[fm][3], bAh + st * STB + aoff[fm]);
            ldm4(al[fm][0], al[fm][1], al[fm][2], al[fm][3], bAl + st * STB + aoff[fm]);
        }
        #pragma unroll
        for (int f = 0; f < 2; f++) {
            ldm4(bh[f][0], bh[f][1], bh[f][2], bh[f][3], bBh + st * STB + boff[f]);
            ldm4(bl[f][0], bl[f][1], bl[f][2], bl[f][3], bBl + st * STB + boff[f]);
        }

        #pragma unroll
        for (int fm = 0; fm < 4; fm++) {
            #pragma unroll
            for (int f = 0; f < 2; f++) {
                mma16816(acc[fm][f * 2 + 0], ah[fm], bh[f][0], bh[f][2]);
                mma16816(acc[fm][f * 2 + 0], ah[fm], bl[f][0], bl[f][2]);
                mma16816(acc[fm][f * 2 + 0], al[fm], bh[f][0], bh[f][2]);
                mma16816(acc[fm][f * 2 + 1], ah[fm], bh[f][1], bh[f][3]);
                mma16816(acc[fm][f * 2 + 1], ah[fm], bl[f][1], bl[f][3]);
                mma16816(acc[fm][f * 2 + 1], al[fm], bh[f][1], bh[f][3]);
            }
        }

        if (t + 1 < nk) {
            const int ns = st ^ 1;
            *reinterpret_cast<uint4*>(&sAh[ns][sidx]) = vah;
            *reinterpret_cast<uint4*>(&sAl[ns][sidx]) = val;
            *reinterpret_cast<uint4*>(&sBh[ns][sidx]) = vbh;
            *reinterpret_cast<uint4*>(&sBl[ns][sidx]) = vbl;
            __syncthreads();
        }
    }

    // epilogue (pairwise: cols cc, cc+1)
    #pragma unroll
    for (int fm = 0; fm < 4; fm++) {
        #pragma unroll
        for (int half = 0; half < 2; half++) {
            const int r = row0 + wm * 64 + fm * 16 + (lane >> 2) + half * 8;
            if (r >= M) continue;
            int bb = 0, ii = 0, jj = 0;
            if (mode == 3 || mode == 4) { bb = r / 500; ii = (r / 50) % 10; jj = r % 50; }
            #pragma unroll
            for (int fn = 0; fn < 4; fn++) {
                const int cc = col0 + wn * 32 + fn * 8 + (lane & 3) * 2;
                if (cc >= N) continue;
                float v0 = acc[fm][fn][half * 2], v1 = acc[fm][fn][half * 2 + 1];
                if (mode == 1) { v0 += aux0[cc]; v1 += aux0[cc + 1]; }
                if (mode == 2) { v0 = tanhf(v0 + aux0[cc]); v1 = tanhf(v1 + aux0[cc + 1]); }
                if (mode == 3) {
                    const float* p0 = aux0 + (size_t)(bb * 50 + jj) * N;
                    const float* p1 = aux1 + (size_t)(bb * 10 + ii) * N;
                    v0 += p0[cc] + p1[cc] + aux2[cc];
                    v1 += p0[cc + 1] + p1[cc + 1] + aux2[cc + 1];
                }
                if (mode == 4) {
                    const float* p0 = aux0 + (size_t)(bb * 10 + ii) * N;
                    v0 = tanhf(v0 + p0[cc]); v1 = tanhf(v1 + p0[cc + 1]);
                }
                if (out & 1)
                    *reinterpret_cast<float2*>(&C[(size_t)r * ldc + cc]) = make_float2(v0, v1);
                if (out & 2) {
                    bf16 h0 = __float2bfloat16_rn(v0), h1 = __float2bfloat16_rn(v1);
                    *reinterpret_cast<uint32_t*>(&Ch[(size_t)r * ldc + cc]) = pk2h(h0, h1);
                    *reinterpret_cast<uint32_t*>(&Cl[(size_t)r * ldc + cc]) =
                        pkbf(v0 - __bfloat162float(h0), v1 - __bfloat162float(h1));
                }
            }
        }
    }
}

// template wrapper (big GEMMs, modes 2/3/4)
template <int MODE, int OUT>
__global__ __launch_bounds__(256) void gemm_mma(
    const bf16* __restrict__ Ah, const bf16* __restrict__ Al, int lda,
    const bf16* __restrict__ Bh, const bf16* __restrict__ Bl, int ldb,
    float* __restrict__ C, bf16* __restrict__ Ch, bf16* __restrict__ Cl,
    int ldc, int M, int N, int K,
    const float* __restrict__ aux0, const float* __restrict__ aux1,
    const float* __restrict__ aux2)
{
    gemm_core(Ah, Al, lda, Bh, Bl, ldb, C, Ch, Cl, ldc, M, N, K,
              aux0, aux1, aux2, blockIdx.y * TBM, blockIdx.x * TBN, MODE, OUT);
}

// grouped wrapper (small GEMMs, modes 0/1)
struct GDesc {
    const bf16 *Ah, *Al, *Bh, *Bl;
    float* C; bf16 *Ch; bf16 *Cl;
    const float* aux0;
    int lda, ldb, ldc, M, N, K, mode, out, bx;
};
struct GParams { GDesc d[6]; int cum[7]; int nd; };

__global__ __launch_bounds__(256) void gemm_group(GParams P) {
    int g = 0;
    while (g + 1 < P.nd && (int)blockIdx.x >= P.cum[g + 1]) g++;
    const GDesc& D = P.d[g];
    int local = blockIdx.x - P.cum[g];
    int bxi = local % D.bx, byi = local / D.bx;
    gemm_core(D.Ah, D.Al, D.lda, D.Bh, D.Bl, D.ldb, D.C, D.Ch, D.Cl, D.ldc,
              D.M, D.N, D.K, D.aux0, nullptr, nullptr,
              byi * TBM, bxi * TBN, D.mode, D.out);
}

// ---------------- attention K/V pre-split ----------------
// K out: [n][h][m][32 padded]   V out: [n][h][d][m]
__global__ void attn_prep(const float* __restrict__ Cq3, const float* __restrict__ Hq3,
                          bf16* __restrict__ KHg, bf16* __restrict__ KLg,
                          bf16* __restrict__ VHg, bf16* __restrict__ VLg)
{
    const int n = blockIdx.x, b = blockIdx.y;
    const float* Hrow = Hq3 + (size_t)(b * NH_ + n) * 1200;
    const bf16 zb = __float2bfloat16_rn(0.f);

    // K: order (h, mm, d)
    for (int idx = threadIdx.x; idx < 4000; idx += 256) {
        int h = idx / 200, mm = (idx / 20) % 10, d = idx % 20;
        int m = b * 10 + mm;
        float kv = Cq3[m * 1200 + 400 + h * 20 + d] + Hrow[400 + h * 20 + d];
        bf16 hh = __float2bfloat16_rn(kv);
        size_t o = ((size_t)(n * 20 + h) * 640 + m) * 32 + d;
        KHg[o] = hh;
        KLg[o] = __float2bfloat16_rn(kv - __bfloat162float(hh));
    }
    // K pads (d 20..31)
    for (int idx = threadIdx.x; idx < 2400; idx += 256) {
        int h = idx / 120, mm = (idx / 12) % 10, d = 20 + idx % 12;
        size_t o = ((size_t)(n * 20 + h) * 640 + b * 10 + mm) * 32 + d;
        KHg[o] = zb; KLg[o] = zb;
    }
    // V: order (h, d, mm)
    for (int idx = threadIdx.x; idx < 4000; idx += 256) {
        int h = idx / 200, d = (idx / 10) % 20, mm = idx % 10;
        int m = b * 10 + mm;
        float vv = Cq3[m * 1200 + 800 + h * 20 + d] + Hrow[800 + h * 20 + d];
        bf16 hh = __float2bfloat16_rn(vv);
        size_t o = ((size_t)(n * 20 + h) * 20 + d) * 640 + m;
        VHg[o] = hh;
        VLg[o] = __float2bfloat16_rn(vv - __bfloat162float(hh));
    }
}

// ---------------- tensor-core flash attention ----------------
// grid (5 qtiles, 50 n, 20 h), 256 threads (8 warps, warp = 16 query rows)
__global__ __launch_bounds__(256) void attn_mma(
    const float* __restrict__ Cq3, const float* __restrict__ Hq3,
    const bf16* __restrict__ KHg, const bf16* __restrict__ KLg,
    const bf16* __restrict__ VHg, const bf16* __restrict__ VLg,
    bf16* __restrict__ Xoh, bf16* __restrict__ Xol)
{
    __shared__ __align__(16) bf16 sm[18944];
    bf16* QH = sm;               // [128][40]
    bf16* QL = sm + 5120;
    bf16* KH = sm;               // reuse after Q frags loaded
    bf16* KL = sm + 5120;
    bf16* VTH = sm + 10240;      // [32][136]
    bf16* VTL = sm + 14592;

    const int qt = blockIdx.x, n = blockIdx.y, h = blockIdx.z;
    const int tid = threadIdx.x, w = tid >> 5, lane = tid & 31;
    const float scale = 0.22360679774997896f;  // 1/sqrt(20)
    const bf16 zb = __float2bfloat16_rn(0.f);

    const bf16* Kbh = KHg + (size_t)(n * 20 + h) * 640 * 32;
    const bf16* Kbl = KLg + (size_t)(n * 20 + h) * 640 * 32;
    const bf16* Vbh = VHg + (size_t)(n * 20 + h) * 20 * 640;
    const bf16* Vbl = VLg + (size_t)(n * 20 + h) * 20 * 640;

    // Phase 1: build Q tile (rows qt*128.., dims 0-19, pad 20-31 zero)
    for (int idx = tid; idx < 128 * 32; idx += 256) {
        int r = idx >> 5, d = idx & 31;
        float v = 0.f;
        if (d < 20) {
            int l = qt * 128 + r;
            int qr = (l / NC_) * NH_ + n;
            v = (Cq3[l * 1200 + h * 20 + d] + Hq3[qr * 1200 + h * 20 + d]) * scale;
        }
        bf16 hh = __float2bfloat16_rn(v);
        QH[r * 40 + d] = hh;
        QL[r * 40 + d] = __float2bfloat16_rn(v - __bfloat162float(hh));
    }
    __syncthreads();

    const int mrow = ((lane >> 3) & 1) * 8 + (lane & 7);
    const int koff = (lane >> 4) * 8;

    uint32_t qh[2][4], ql[2][4];
    #pragma unroll
    for (int kc = 0; kc < 2; kc++) {
        uint32_t a = (uint32_t)(((w * 16 + mrow) * 40 + kc * 16 + koff) * 2);
        ldm4(qh[kc][0], qh[kc][1], qh[kc][2], qh[kc][3], s2u(QH) + a);
        ldm4(ql[kc][0], ql[kc][1], ql[kc][2], ql[kc][3], s2u(QL) + a);
    }
    __syncthreads();

    // zero VT pad rows 20-31
    for (int idx = tid; idx < 12 * 136; idx += 256) {
        int d = 20 + idx / 136, k = idx % 136;
        VTH[d * 136 + k] = zb; VTL[d * 136 + k] = zb;
    }

    float O0[3][4];
    #pragma unroll
    for (int f = 0; f < 3; f++)
        #pragma unroll
        for (int e = 0; e < 4; e++) O0[f][e] = 0.f;
    float zl = 0.f, zh2 = 0.f;

    for (int kt = 0; kt < 5; kt++) {
        __syncthreads();
        // copy K tile: 128 rows x 32 cols (split) — pure uint4 copies
        for (int i = tid; i < 512; i += 256) {
            int kk = i >> 2, q = (i & 3) * 8;
            size_t src = (size_t)(kt * 128 + kk) * 32 + q;
            *reinterpret_cast<uint4*>(&KH[kk * 40 + q]) =
                *reinterpret_cast<const uint4*>(&Kbh[src]);
            *reinterpret_cast<uint4*>(&KL[kk * 40 + q]) =
                *reinterpret_cast<const uint4*>(&Kbl[src]);
        }
        // copy V tile: 20 d-rows x 128 keys (split)
        for (int i = tid; i < 320; i += 256) {
            int d = i >> 4, cc = (i & 15) * 8;
            size_t src = (size_t)d * 640 + kt * 128 + cc;
            *reinterpret_cast<uint4*>(&VTH[d * 136 + cc]) =
                *reinterpret_cast<const uint4*>(&Vbh[src]);
            *reinterpret_cast<uint4*>(&VTL[d * 136 + cc]) =
                *reinterpret_cast<const uint4*>(&Vbl[src]);
        }
        __syncthreads();

        // S = Q K^T  (16 n8 frags x 4 fp32)
        union { float f[16][4]; uint32_t u[16][4]; } SP;
        #pragma unroll
        for (int f = 0; f < 16; f++)
            #pragma unroll
            for (int e = 0; e < 4; e++) SP.f[f][e] = 0.f;

        #pragma unroll
        for (int g = 0; g < 8; g++) {
            uint32_t kh[2][4], kl[2][4];
            #pragma unroll
            for (int kc = 0; kc < 2; kc++) {
                uint32_t a = (uint32_t)(((g * 16 + mrow) * 40 + kc * 16 + koff) * 2);
                ldm4(kh[kc][0], kh[kc][1], kh[kc][2], kh[kc][3], s2u(KH) + a);
                ldm4(kl[kc][0], kl[kc][1], kl[kc][2], kl[kc][3], s2u(KL) + a);
            }
            #pragma unroll
            for (int kc = 0; kc < 2; kc++) {
                mma16816(SP.f[2 * g + 0], qh[kc], kh[kc][0], kh[kc][2]);
                mma16816(SP.f[2 * g + 0], qh[kc], kl[kc][0], kl[kc][2]);
                mma16816(SP.f[2 * g + 0], ql[kc], kh[kc][0], kh[kc][2]);
                mma16816(SP.f[2 * g + 1], qh[kc], kh[kc][1], kh[kc][3]);
                mma16816(SP.f[2 * g + 1], qh[kc], kl[kc][1], kl[kc][3]);
                mma16816(SP.f[2 * g + 1], ql[kc], kh[kc][1], kh[kc][3]);
            }
        }

        // exp + split P (in place)
        #pragma unroll
        for (int f = 0; f < 16; f++) {
            float e0 = __expf(SP.f[f][0]), e1 = __expf(SP.f[f][1]);
            float e2 = __expf(SP.f[f][2]), e3 = __expf(SP.f[f][3]);
            zl += e0 + e1; zh2 += e2 + e3;
            bf16 h0 = __float2bfloat16_rn(e0), h1 = __float2bfloat16_rn(e1);
            bf16 h2 = __float2bfloat16_rn(e2), h3 = __float2bfloat16_rn(e3);
            uint32_t ph01 = pk2h(h0, h1), ph23 = pk2h(h2, h3);
            uint32_t pl01 = pkbf(e0 - __bfloat162float(h0), e1 - __bfloat162float(h1));
            uint32_t pl23 = pkbf(e2 - __bfloat162float(h2), e3 - __bfloat162float(h3));
            SP.u[f][0] = ph01; SP.u[f][1] = ph23; SP.u[f][2] = pl01; SP.u[f][3] = pl23;
        }

        // O += P V
        #pragma unroll
        for (int kc2 = 0; kc2 < 8; kc2++) {
            uint32_t ah[4] = { SP.u[2 * kc2][0], SP.u[2 * kc2][1],
                               SP.u[2 * kc2 + 1][0], SP.u[2 * kc2 + 1][1] };
            uint32_t al[4] = { SP.u[2 * kc2][2], SP.u[2 * kc2][3],
                               SP.u[2 * kc2 + 1][2], SP.u[2 * kc2 + 1][3] };
            uint32_t vh4[4], vl4[4], vh2[2], vl2[2];
            uint32_t a4 = (uint32_t)((mrow * 136 + kc2 * 16 + koff) * 2);
            uint32_t a2 = (uint32_t)(((16 + (lane & 7)) * 136 + kc2 * 16 + ((lane >> 3) & 1) * 8) * 2);
            ldm4(vh4[0], vh4[1], vh4[2], vh4[3], s2u(VTH) + a4);
            ldm4(vl4[0], vl4[1], vl4[2], vl4[3], s2u(VTL) + a4);
            ldm2(vh2[0], vh2[1], s2u(VTH) + a2);
            ldm2(vl2[0], vl2[1], s2u(VTL) + a2);
            mma16816(O0[0], ah, vh4[0], vh4[2]);
            mma16816(O0[0], ah, vl4[0], vl4[2]);
            mma16816(O0[0], al, vh4[0], vh4[2]);
            mma16816(O0[1], ah, vh4[1], vh4[3]);
            mma16816(O0[1], ah, vl4[1], vl4[3]);
            mma16816(O0[1], al, vh4[1], vh4[3]);
            mma16816(O0[2], ah, vh2[0], vh2[1]);
            mma16816(O0[2], ah, vl2[0], vl2[1]);
            mma16816(O0[2], al, vh2[0], vh2[1]);
        }
    }

    // Z reduction within quads
    zl  += __shfl_xor_sync(0xffffffffu, zl, 1);
    zl  += __shfl_xor_sync(0xffffffffu, zl, 2);
    zh2 += __shfl_xor_sync(0xffffffffu, zh2, 1);
    zh2 += __shfl_xor_sync(0xffffffffu, zh2, 2);
    float izl = 1.f / zl, izh = 1.f / zh2;

    // store O (bf16 split) -> Xo[(l*50+n)*400 + h*20 + d]
    const int rowq = lane >> 2;
    #pragma unroll
    for (int f = 0; f < 3; f++) {
        int d0 = f * 8 + (lane & 3) * 2;
        if (d0 >= 20) continue;
        #pragma unroll
        for (int half = 0; half < 2; half++) {
            int lq = qt * 128 + w * 16 + rowq + half * 8;
            float v0 = O0[f][half * 2]     * (half ? izh : izl);
            float v1 = O0[f][half * 2 + 1] * (half ? izh : izl);
            size_t o = (size_t)(lq * NH_ + n) * 400 + h * 20 + d0;
            bf16 h0 = __float2bfloat16_rn(v0), h1 = __float2bfloat16_rn(v1);
            *reinterpret_cast<uint32_t*>(&Xoh[o]) = pk2h(h0, h1);
            *reinterpret_cast<uint32_t*>(&Xol[o]) =
                pkbf(v0 - __bfloat162float(h0), v1 - __bfloat162float(h1));
        }
    }
}

// ---------------- score + softmax ----------------
__global__ void score_kernel(const float* __restrict__ a2, const float* __restrict__ Wa3,
                             const float* __restrict__ ba3, float* __restrict__ s)
{
    int row = blockIdx.x * 8 + threadIdx.y;
    if (row >= MM) return;
    int lane = threadIdx.x;
    float acc = 0.f;
    for (int d = lane; d < 200; d += 32) acc += a2[(size_t)row * 200 + d] * Wa3[d];
    #pragma unroll
    for (int o = 16; o > 0; o >>= 1) acc += __shfl_xor_sync(0xffffffffu, acc, o);
    if (lane == 0) s[row] = acc + ba3[0];
}

__global__ void softmax_u_kernel(const float* __restrict__ s, const float* __restrict__ hall,
                                 float* __restrict__ u)
{
    __shared__ float a[NH_];
    int bi = blockIdx.x;
    if (threadIdx.x == 0) {
        float mx = -1e30f;
        for (int j = 0; j < NH_; j++) mx = fmaxf(mx, s[bi * NH_ + j]);
        float Z = 0.f;
        for (int j = 0; j < NH_; j++) { float e = __expf(s[bi * NH_ + j] - mx); a[j] = e; Z += e; }
        float iz = 1.f / Z;
        for (int j = 0; j < NH_; j++) a[j] *= iz;
    }
    __syncthreads();
    for (int d = threadIdx.x; d < 400; d += blockDim.x) {
        float acc = 0.f;
        for (int j = 0; j < NH_; j++)
            acc += a[j] * hall[((size_t)bi * NH_ + j) * 400 + d];
        u[(size_t)bi * 400 + d] = acc;
    }
}

// ---------------- launch ----------------
static inline dim3 mgrid(int M, int N) { return dim3((N + TBN - 1) / TBN, (M + TBM - 1) / TBM); }

extern "C" void kernel_launch(void* const* d_in, const int* in_sizes, int n_in,
                              void* d_out, int out_size)
{
    const float* h    = (const float*)d_in[0];
    const float* c    = (const float*)d_in[2];
    const float* W1   = (const float*)d_in[4];
    const float* b1   = (const float*)d_in[5];
    const float* W2   = (const float*)d_in[6];
    const float* b2   = (const float*)d_in[7];
    const float* W3   = (const float*)d_in[8];
    const float* b3   = (const float*)d_in[9];
    const float* Wa1  = (const float*)d_in[10];
    const float* ba1  = (const float*)d_in[11];
    const float* Wa2  = (const float*)d_in[12];
    const float* ba2  = (const float*)d_in[13];
    const float* Wa3  = (const float*)d_in[14];
    const float* ba3  = (const float*)d_in[15];
    const float* Wqkv = (const float*)d_in[16];
    const float* bqkv = (const float*)d_in[17];
    const float* Wo   = (const float*)d_in[18];
    const float* bo   = (const float*)d_in[19];
    float* u = (float*)d_out;

    float *Hq3, *Cq3, *T1, *T2, *tc, *CA, *hall, *a2, *sc;
    cudaGetSymbolAddress((void**)&Hq3,  g_Hq3);
    cudaGetSymbolAddress((void**)&Cq3,  g_Cq3);
    cudaGetSymbolAddress((void**)&T1,   g_T1);
    cudaGetSymbolAddress((void**)&T2,   g_T2);
    cudaGetSymbolAddress((void**)&tc,   g_tc);
    cudaGetSymbolAddress((void**)&CA,   g_CA);
    cudaGetSymbolAddress((void**)&hall, g_hall);
    cudaGetSymbolAddress((void**)&a2,   g_a2);
    cudaGetSymbolAddress((void**)&sc,   g_s);

    bf16 *bHcat_h, *bHcat_l, *bh_h, *bh_l, *bHs_h, *bHs_l, *bHp1_h, *bHp1_l;
    bf16 *bc_h, *bc_l, *bCc_h, *bCc_l, *bCs_h, *bCs_l;
    bf16 *bXo_h, *bXo_l, *bhall_h, *bhall_l, *ba1_h, *ba1_l;
    bf16 *bW1_h, *bW1_l, *bW2_h, *bW2_l, *bWqkv_h, *bWqkv_l, *bW3_h, *bW3_l;
    bf16 *bWa1_h, *bWa1_l, *bWa2_h, *bWa2_l, *bWoT_h, *bWoT_l, *bWm_h, *bWm_l;
    bf16 *KHg, *KLg, *VHg, *VLg;
    cudaGetSymbolAddress((void**)&bHcat_h, g_bHcat_h);  cudaGetSymbolAddress((void**)&bHcat_l, g_bHcat_l);
    cudaGetSymbolAddress((void**)&bh_h,    g_bh_h);     cudaGetSymbolAddress((void**)&bh_l,    g_bh_l);
    cudaGetSymbolAddress((void**)&bHs_h,   g_bHs_h);    cudaGetSymbolAddress((void**)&bHs_l,   g_bHs_l);
    cudaGetSymbolAddress((void**)&bHp1_h,  g_bHp1_h);   cudaGetSymbolAddress((void**)&bHp1_l,  g_bHp1_l);
    cudaGetSymbolAddress((void**)&bc_h,    g_bc_h);     cudaGetSymbolAddress((void**)&bc_l,    g_bc_l);
    cudaGetSymbolAddress((void**)&bCc_h,   g_bCc_h);    cudaGetSymbolAddress((void**)&bCc_l,   g_bCc_l);
    cudaGetSymbolAddress((void**)&bCs_h,   g_bCs_h);    cudaGetSymbolAddress((void**)&bCs_l,   g_bCs_l);
    cudaGetSymbolAddress((void**)&bXo_h,   g_bXo_h);    cudaGetSymbolAddress((void**)&bXo_l,   g_bXo_l);
    cudaGetSymbolAddress((void**)&bhall_h, g_bhall_h);  cudaGetSymbolAddress((void**)&bhall_l, g_bhall_l);
    cudaGetSymbolAddress((void**)&ba1_h,   g_ba1_h);    cudaGetSymbolAddress((void**)&ba1_l,   g_ba1_l);
    cudaGetSymbolAddress((void**)&bW1_h,   g_bW1_h);    cudaGetSymbolAddress((void**)&bW1_l,   g_bW1_l);
    cudaGetSymbolAddress((void**)&bW2_h,   g_bW2_h);    cudaGetSymbolAddress((void**)&bW2_l,   g_bW2_l);
    cudaGetSymbolAddress((void**)&bWqkv_h, g_bWqkv_h);  cudaGetSymbolAddress((void**)&bWqkv_l, g_bWqkv_l);
    cudaGetSymbolAddress((void**)&bW3_h,   g_bW3_h);    cudaGetSymbolAddress((void**)&bW3_l,   g_bW3_l);
    cudaGetSymbolAddress((void**)&bWa1_h,  g_bWa1_h);   cudaGetSymbolAddress((void**)&bWa1_l,  g_bWa1_l);
    cudaGetSymbolAddress((void**)&bWa2_h,  g_bWa2_h);   cudaGetSymbolAddress((void**)&bWa2_l,  g_bWa2_l);
    cudaGetSymbolAddress((void**)&bWoT_h,  g_bWoT_h);   cudaGetSymbolAddress((void**)&bWoT_l,  g_bWoT_l);
    cudaGetSymbolAddress((void**)&bWm_h,   g_bWm_h);    cudaGetSymbolAddress((void**)&bWm_l,   g_bWm_l);
    cudaGetSymbolAddress((void**)&KHg, g_KHg);  cudaGetSymbolAddress((void**)&KLg, g_KLg);
    cudaGetSymbolAddress((void**)&VHg, g_VHg);  cudaGetSymbolAddress((void**)&VLg, g_VLg);

    // ---- merged conversions (one launch) ----
    ConvParams CP;
    const float* srcs[8] = { h, c, W1, W2, Wqkv, W3, Wa1, Wa2 };
    bf16* his[8] = { bh_h, bc_h, bW1_h, bW2_h, bWqkv_h, bW3_h, bWa1_h, bWa2_h };
    bf16* los[8] = { bh_l, bc_l, bW1_l, bW2_l, bWqkv_l, bW3_l, bWa1_l, bWa2_l };
    int ns[8] = { BNH * 400, LL * 400, 400 * 1600, 400 * 800, 1200 * 400,
                  400 * 800, 400 * 800, 200 * 400 };
    int cum = 0;
    for (int i = 0; i < 8; i++) { CP.src[i] = srcs[i]; CP.hi[i] = his[i]; CP.lo[i] = los[i];
                                  CP.cum[i] = cum; cum += ns[i]; }
    CP.cum[8] = cum;
    conv_all_kernel<<<(cum + 255) / 256, 256>>>(CP);

    build_hcat_bf16<<<(BNH * 600 + 255) / 256, 256>>>(bh_h, bh_l, bHcat_h, bHcat_l);
    transpose_split_kernel<<<(400 * 400 + 255) / 256, 256>>>(Wo, bWoT_h, bWoT_l);
    tc_kernel<<<2, 256>>>(b1, bo, b3, W3, tc);

    // ---- grouped GEMM launch 1: independent small GEMMs ----
    {
        GParams G; int cumb = 0; int gi = 0;
        auto add = [&](const bf16* Ah, const bf16* Al, int lda,
                       const bf16* Bh, const bf16* Bl, int ldb,
                       float* C, bf16* Ch, bf16* Cl, int ldc,
                       int M, int N, int K, int mode, int out, const float* aux0) {
            GDesc& D = G.d[gi];
            D.Ah = Ah; D.Al = Al; D.Bh = Bh; D.Bl = Bl;
            D.C = C; D.Ch = Ch; D.Cl = Cl; D.aux0 = aux0;
            D.lda = lda; D.ldb = ldb; D.ldc = ldc; D.M = M; D.N = N; D.K = K;
            D.mode = mode; D.out = out;
            D.bx = (N + TBN - 1) / TBN;
            int by = (M + TBM - 1) / TBM;
            G.cum[gi] = cumb; cumb += D.bx * by; gi++;
        };
        add(bHcat_h, bHcat_l, 1200, bW1_h, bW1_l, 1600, nullptr, bHp1_h, bHp1_l, 400,
            BNH, 400, 1200, 0, 2, nullptr);                                   // Hp1
        add(bh_h, bh_l, 400, bW2_h + 400, bW2_l + 400, 800, nullptr, bHs_h, bHs_l, 400,
            BNH, 400, 400, 0, 2, nullptr);                                    // Hs
        add(bc_h, bc_l, 400, bW1_h + 1200, bW1_l + 1200, 1600, nullptr, bCc_h, bCc_l, 400,
            LL, 400, 400, 0, 2, nullptr);                                     // Cc
        add(bc_h, bc_l, 400, bW2_h, bW2_l, 800, nullptr, bCs_h, bCs_l, 400,
            LL, 400, 400, 1, 2, b2);                                          // Cs
        add(bc_h, bc_l, 400, bWa1_h + 400, bWa1_l + 400, 800, CA, nullptr, nullptr, 400,
            LL, 400, 400, 1, 1, ba1);                                         // CA
        add(bW3_h + 400, bW3_l + 400, 800, bWoT_h, bWoT_l, 400, nullptr, bWm_h, bWm_l, 400,
            400, 400, 400, 0, 2, nullptr);                                    // Wm
        G.cum[gi] = cumb; G.nd = gi;
        gemm_group<<<cumb, 256>>>(G);
    }

    // ---- grouped GEMM launch 2: dependent small GEMMs ----
    {
        GParams G; int cumb = 0; int gi = 0;
        auto add = [&](const bf16* Ah, const bf16* Al, int lda,
                       const bf16* Bh, const bf16* Bl, int ldb,
                       float* C, int ldc, int M, int N, int K, int mode, const float* aux0) {
            GDesc& D = G.d[gi];
            D.Ah = Ah; D.Al = Al; D.Bh = Bh; D.Bl = Bl;
            D.C = C; D.Ch = nullptr; D.Cl = nullptr; D.aux0 = aux0;
            D.lda = lda; D.ldb = ldb; D.ldc = ldc; D.M = M; D.N = N; D.K = K;
            D.mode = mode; D.out = 1;
            D.bx = (N + TBN - 1) / TBN;
            int by = (M + TBM - 1) / TBM;
            G.cum[gi] = cumb; cumb += D.bx * by; gi++;
        };
        add(bHp1_h, bHp1_l, 400, bW3_h, bW3_l, 800, T1, 400, BNH, 400, 400, 0, nullptr);   // T1
        add(bHs_h, bHs_l, 400, bWqkv_h, bWqkv_l, 400, Hq3, 1200, BNH, 1200, 400, 0, nullptr); // Hq3
        add(bCs_h, bCs_l, 400, bWqkv_h, bWqkv_l, 400, Cq3, 1200, LL, 1200, 400, 1, bqkv);  // Cq3
        add(bCc_h, bCc_l, 400, bW3_h, bW3_l, 800, T2, 400, LL, 400, 400, 0, nullptr);      // T2
        G.cum[gi] = cumb; G.nd = gi;
        gemm_group<<<cumb, 256>>>(G);
    }

    // ---- attention: K/V pre-split, then tensor-core flash ----
    attn_prep<<<dim3(NH_, BB), 256>>>(Cq3, Hq3, KHg, KLg, VHg, VLg);
    attn_mma<<<dim3(5, NH_, NHEAD), 256>>>(Cq3, Hq3, KHg, KLg, VHg, VLg, bXo_h, bXo_l);

    // ---- big GEMMs ----
    gemm_mma<3, 3><<<mgrid(MM, 400), 256>>>(bXo_h, bXo_l, 400, bWm_h, bWm_l, 400,
        hall, bhall_h, bhall_l, 400, MM, 400, 400, T1, T2, tc);
    gemm_mma<4, 2><<<mgrid(MM, 400), 256>>>(bhall_h, bhall_l, 400, bWa1_h, bWa1_l, 800,
        nullptr, ba1_h, ba1_l, 400, MM, 400, 400, CA, nullptr, nullptr);
    gemm_mma<2, 1><<<mgrid(MM, 200), 256>>>(ba1_h, ba1_l, 400, bWa2_h, bWa2_l, 400,
        a2, nullptr, nullptr, 200, MM, 200, 400, ba2, nullptr, nullptr);

    // ---- scoring + softmax + weighted sum ----
    score_kernel<<<MM / 8, dim3(32, 8)>>>(a2, Wa3, ba3, sc);
    softmax_u_kernel<<<LL, 128>>>(sc, hall, u);
}

// round 8
// speedup vs baseline: 2.1330x; 1.0486x over previous
#include <cuda_runtime.h>
#include <cuda_bf16.h>
#include <math.h>
#include <stdint.h>

// Problem constants
#define DD    400
#define BB    64
#define NC_   10
#define NH_   50
#define NHEAD 20
#define DH    20
#define LL    640      // BB*NC_
#define MM    32000    // BB*NC_*NH_
#define BNH   3200     // BB*NH_

typedef __nv_bfloat16 bf16;

// ---------------- fp32 device scratch ----------------
__device__ float g_Hq3 [BNH * 1200];
__device__ float g_Cq3 [LL * 1200];
__device__ float g_T1  [BNH * 400];
__device__ float g_T2  [LL * 400];
__device__ float g_tc  [400];
__device__ float g_CA  [LL * 400];
__device__ float g_hall[MM * 400];
__device__ float g_a2  [MM * 200];
__device__ float g_s   [MM];

// ---------------- bf16 split scratch (hi/lo pairs) ----------------
__device__ __align__(16) bf16 g_bHcat_h[BNH * 1200], g_bHcat_l[BNH * 1200];
__device__ __align__(16) bf16 g_bh_h  [BNH * 400],  g_bh_l  [BNH * 400];
__device__ __align__(16) bf16 g_bHs_h [BNH * 400],  g_bHs_l [BNH * 400];
__device__ __align__(16) bf16 g_bHp1_h[BNH * 400],  g_bHp1_l[BNH * 400];
__device__ __align__(16) bf16 g_bc_h  [LL * 400],   g_bc_l  [LL * 400];
__device__ __align__(16) bf16 g_bCc_h [LL * 400],   g_bCc_l [LL * 400];
__device__ __align__(16) bf16 g_bCs_h [LL * 400],   g_bCs_l [LL * 400];
__device__ __align__(16) bf16 g_bXo_h [MM * 400],   g_bXo_l [MM * 400];
__device__ __align__(16) bf16 g_bhall_h[MM * 400],  g_bhall_l[MM * 400];
__device__ __align__(16) bf16 g_ba1_h [MM * 400],   g_ba1_l [MM * 400];
__device__ __align__(16) bf16 g_bW1_h [400 * 1600], g_bW1_l [400 * 1600];
__device__ __align__(16) bf16 g_bW2_h [400 * 800],  g_bW2_l [400 * 800];
__device__ __align__(16) bf16 g_bWqkv_h[1200 * 400],g_bWqkv_l[1200 * 400];
__device__ __align__(16) bf16 g_bW3_h [400 * 800],  g_bW3_l [400 * 800];
__device__ __align__(16) bf16 g_bWa1_h[400 * 800],  g_bWa1_l[400 * 800];
__device__ __align__(16) bf16 g_bWa2_h[200 * 400],  g_bWa2_l[200 * 400];
__device__ __align__(16) bf16 g_bWoT_h[400 * 400],  g_bWoT_l[400 * 400];
__device__ __align__(16) bf16 g_bWm_h [400 * 400],  g_bWm_l [400 * 400];

// attention pre-split K/V
// K: [n][h][m(640)][32 padded]   V: [n][h][d(20)][m(640)]
__device__ __align__(16) bf16 g_KHg[50 * 20 * 640 * 32], g_KLg[50 * 20 * 640 * 32];
__device__ __align__(16) bf16 g_VHg[50 * 20 * 20 * 640], g_VLg[50 * 20 * 20 * 640];

// ---------------- helpers ----------------
__device__ __forceinline__ uint32_t s2u(const void* p) {
    return (uint32_t)__cvta_generic_to_shared(p);
}
__device__ __forceinline__ void ldm4(uint32_t& r0, uint32_t& r1, uint32_t& r2, uint32_t& r3,
                                     uint32_t addr) {
    asm volatile("ldmatrix.sync.aligned.m8n8.x4.shared.b16 {%0,%1,%2,%3}, [%4];"
                 : "=r"(r0), "=r"(r1), "=r"(r2), "=r"(r3) : "r"(addr));
}
__device__ __forceinline__ void ldm2(uint32_t& r0, uint32_t& r1, uint32_t addr) {
    asm volatile("ldmatrix.sync.aligned.m8n8.x2.shared.b16 {%0,%1}, [%2];"
                 : "=r"(r0), "=r"(r1) : "r"(addr));
}
__device__ __forceinline__ void mma16816(float* d, const uint32_t* a, uint32_t b0, uint32_t b1) {
    asm volatile("mma.sync.aligned.m16n8k16.row.col.f32.bf16.bf16.f32 "
                 "{%0,%1,%2,%3}, {%4,%5,%6,%7}, {%8,%9}, {%0,%1,%2,%3};"
                 : "+f"(d[0]), "+f"(d[1]), "+f"(d[2]), "+f"(d[3])
                 : "r"(a[0]), "r"(a[1]), "r"(a[2]), "r"(a[3]), "r"(b0), "r"(b1));
}
__device__ __forceinline__ uint32_t pkbf(float a, float b) {
    __nv_bfloat162 t = __floats2bfloat162_rn(a, b);
    return *reinterpret_cast<uint32_t*>(&t);
}
__device__ __forceinline__ uint32_t pk2h(bf16 a, bf16 b) {
    __nv_bfloat162 t; t.x = a; t.y = b;
    return *reinterpret_cast<uint32_t*>(&t);
}

// ---------------- merged convert: 8 segments in one launch ----------------
struct ConvParams {
    const float* src[8];
    bf16* hi[8];
    bf16* lo[8];
    int cum[9];
};
__global__ void conv_all_kernel(ConvParams P) {
    int i = blockIdx.x * blockDim.x + threadIdx.x;
    if (i >= P.cum[8]) return;
    int g = 0;
    #pragma unroll
    for (int s = 1; s < 8; s++) if (i >= P.cum[s]) g = s;
    int local = i - P.cum[g];
    float v = P.src[g][local];
    bf16 hh = __float2bfloat16_rn(v);
    P.hi[g][local] = hh;
    P.lo[g][local] = __float2bfloat16_rn(v - __bfloat162float(hh));
}

// ---------------- prep2: Hcat gather (bf16 pairs) + Wo transpose-split, one launch ----------------
#define HC_PAIRS (BNH * 600)
#define HC_BLOCKS ((HC_PAIRS + 255) / 256)
#define TR_BLOCKS ((400 * 400 + 255) / 256)
__global__ void prep2_kernel(const bf16* __restrict__ hh, const bf16* __restrict__ hl,
                             bf16* __restrict__ oh, bf16* __restrict__ ol,
                             const float* __restrict__ Wo,
                             bf16* __restrict__ th, bf16* __restrict__ tl) {
    if ((int)blockIdx.x < HC_BLOCKS) {
        int idx = blockIdx.x * blockDim.x + threadIdx.x;   // pairs
        if (idx >= HC_PAIRS) return;
        int row = idx / 600, pr = idx % 600;
        int col = pr * 2;
        int b = row / NH_, j = row % NH_;
        int part = col / 400, d = col % 400;
        int jj = (part == 0) ? (j + NH_ - 1) % NH_ : ((part == 1) ? j : (j + 1) % NH_);
        int s = (b * NH_ + jj) * 400 + d;
        reinterpret_cast<uint32_t*>(oh)[idx] = *reinterpret_cast<const uint32_t*>(&hh[s]);
        reinterpret_cast<uint32_t*>(ol)[idx] = *reinterpret_cast<const uint32_t*>(&hl[s]);
    } else {
        int idx = (blockIdx.x - HC_BLOCKS) * blockDim.x + threadIdx.x;
        if (idx >= 400 * 400) return;
        int n = idx / 400, k = idx % 400;
        float v = Wo[k * 400 + n];
        bf16 hv = __float2bfloat16_rn(v);
        th[idx] = hv;
        tl[idx] = __float2bfloat16_rn(v - __bfloat162float(hv));
    }
}

// ---------------- tc: warp-per-row reduction (grid 50 x 256) ----------------
__global__ void tc_kernel(const float* __restrict__ b1, const float* __restrict__ bo,
                          const float* __restrict__ b3, const float* __restrict__ W3,
                          float* __restrict__ tc) {
    int w = threadIdx.x >> 5, lane = threadIdx.x & 31;
    int r = blockIdx.x * 8 + w;
    if (r >= 400) return;
    const float* row = W3 + (size_t)r * 800;
    float acc = 0.f;
    for (int d = lane; d < 400; d += 32)
        acc += b1[d] * row[d] + bo[d] * row[400 + d];
    #pragma unroll
    for (int o = 16; o > 0; o >>= 1) acc += __shfl_xor_sync(0xffffffffu, acc, o);
    if (lane == 0) tc[r] = acc + b3[r];
}

// ---------------- shared tensor-core GEMM core (bf16 2-way split, 3 MMAs) ----------------
#define TBM 128
#define TBN 128
#define TBK 16
#define SSTR 24

__device__ __forceinline__ void gemm_core(
    const bf16* __restrict__ Ah, const bf16* __restrict__ Al, int lda,
    const bf16* __restrict__ Bh, const bf16* __restrict__ Bl, int ldb,
    float* __restrict__ C, bf16* __restrict__ Ch, bf16* __restrict__ Cl,
    int ldc, int M, int N, int K,
    const float* __restrict__ aux0, const float* __restrict__ aux1,
    const float* __restrict__ aux2,
    int row0, int col0, int mode, int out)
{
    __shared__ __align__(16) bf16 sAh[2][TBM * SSTR];
    __shared__ __align__(16) bf16 sAl[2][TBM * SSTR];
    __shared__ __align__(16) bf16 sBh[2][TBM * SSTR];
    __shared__ __align__(16) bf16 sBl[2][TBM * SSTR];

    const int tid = threadIdx.x;
    const int lrow = tid >> 1, lhalf = tid & 1;

    const bool aok = (row0 + lrow) < M;
    const bool bok = (col0 + lrow) < N;
    const int arow = aok ? (row0 + lrow) : 0;
    const int brow = bok ? (col0 + lrow) : 0;
    const bf16* Aph = Ah + (size_t)arow * lda + lhalf * 8;
    const bf16* Apl = Al + (size_t)arow * lda + lhalf * 8;
    const bf16* Bph = Bh + (size_t)brow * ldb + lhalf * 8;
    const bf16* Bpl = Bl + (size_t)brow * ldb + lhalf * 8;
    const int sidx = lrow * SSTR + lhalf * 8;

    const int w = tid >> 5, lane = tid & 31;
    const int wm = w >> 2, wn = w & 3;
    const int mrow = ((lane >> 3) & 1) * 8 + (lane & 7);
    const int koff = (lane >> 4) * 8;

    uint32_t aoff[4], boff[2];
    #pragma unroll
    for (int fm = 0; fm < 4; fm++)
        aoff[fm] = (uint32_t)(((wm * 64 + fm * 16 + mrow) * SSTR + koff) * 2);
    #pragma unroll
    for (int f = 0; f < 2; f++)
        boff[f] = (uint32_t)(((wn * 32 + f * 16 + mrow) * SSTR + koff) * 2);

    const uint32_t bAh = s2u(sAh), bAl = s2u(sAl), bBh = s2u(sBh), bBl = s2u(sBl);
    const uint32_t STB = TBM * SSTR * 2;

    float acc[4][4][4];
    #pragma unroll
    for (int i = 0; i < 4; i++)
        #pragma unroll
        for (int j = 0; j < 4; j++)
            #pragma unroll
            for (int e = 0; e < 4; e++) acc[i][j][e] = 0.f;

    const uint4 z4 = make_uint4(0u, 0u, 0u, 0u);
    {
        uint4 vah = aok ? *reinterpret_cast<const uint4*>(Aph) : z4;
        uint4 val = aok ? *reinterpret_cast<const uint4*>(Apl) : z4;
        uint4 vbh = bok ? *reinterpret_cast<const uint4*>(Bph) : z4;
        uint4 vbl = bok ? *reinterpret_cast<const uint4*>(Bpl) : z4;
        *reinterpret_cast<uint4*>(&sAh[0][sidx]) = vah;
        *reinterpret_cast<uint4*>(&sAl[0][sidx]) = val;
        *reinterpret_cast<uint4*>(&sBh[0][sidx]) = vbh;
        *reinterpret_cast<uint4*>(&sBl[0][sidx]) = vbl;
    }
    __syncthreads();

    const int nk = K / TBK;
    for (int t = 0; t < nk; t++) {
        const int st = t & 1;
        uint4 vah, val, vbh, vbl;
        if (t + 1 < nk) {
            const int k = (t + 1) * TBK;
            vah = aok ? *reinterpret_cast<const uint4*>(Aph + k) : z4;
            val = aok ? *reinterpret_cast<const uint4*>(Apl + k) : z4;
            vbh = bok ? *reinterpret_cast<const uint4*>(Bph + k) : z4;
            vbl = bok ? *reinterpret_cast<const uint4*>(Bpl + k) : z4;
        }

        uint32_t ah[4][4], al[4][4], bh[2][4], bl[2][4];
        #pragma unroll
        for (int fm = 0; fm < 4; fm++) {
            ldm4(ah[fm][0], ah[fm][1], ah[fm][2], ah[fm][3], bAh + st * STB + aoff[fm]);
            ldm4(al[fm][0], al[fm][1], al[fm][2], al[fm][3], bAl + st * STB + aoff[fm]);
        }
        #pragma unroll
        for (int f = 0; f < 2; f++) {
            ldm4(bh[f][0], bh[f][1], bh[f][2], bh[f][3], bBh + st * STB + boff[f]);
            ldm4(bl[f][0], bl[f][1], bl[f][2], bl[f][3], bBl + st * STB + boff[f]);
        }

        #pragma unroll
        for (int fm = 0; fm < 4; fm++) {
            #pragma unroll
            for (int f = 0; f < 2; f++) {
                mma16816(acc[fm][f * 2 + 0], ah[fm], bh[f][0], bh[f][2]);
                mma16816(acc[fm][f * 2 + 0], ah[fm], bl[f][0], bl[f][2]);
                mma16816(acc[fm][f * 2 + 0], al[fm], bh[f][0], bh[f][2]);
                mma16816(acc[fm][f * 2 + 1], ah[fm], bh[f][1], bh[f][3]);
                mma16816(acc[fm][f * 2 + 1], ah[fm], bl[f][1], bl[f][3]);
                mma16816(acc[fm][f * 2 + 1], al[fm], bh[f][1], bh[f][3]);
            }
        }

        if (t + 1 < nk) {
            const int ns = st ^ 1;
            *reinterpret_cast<uint4*>(&sAh[ns][sidx]) = vah;
            *reinterpret_cast<uint4*>(&sAl[ns][sidx]) = val;
            *reinterpret_cast<uint4*>(&sBh[ns][sidx]) = vbh;
            *reinterpret_cast<uint4*>(&sBl[ns][sidx]) = vbl;
            __syncthreads();
        }
    }

    // epilogue (pairwise: cols cc, cc+1)
    #pragma unroll
    for (int fm = 0; fm < 4; fm++) {
        #pragma unroll
        for (int half = 0; half < 2; half++) {
            const int r = row0 + wm * 64 + fm * 16 + (lane >> 2) + half * 8;
            if (r >= M) continue;
            int bb = 0, ii = 0, jj = 0;
            if (mode == 3 || mode == 4) { bb = r / 500; ii = (r / 50) % 10; jj = r % 50; }
            #pragma unroll
            for (int fn = 0; fn < 4; fn++) {
                const int cc = col0 + wn * 32 + fn * 8 + (lane & 3) * 2;
                if (cc >= N) continue;
                float v0 = acc[fm][fn][half * 2], v1 = acc[fm][fn][half * 2 + 1];
                if (mode == 1) { v0 += aux0[cc]; v1 += aux0[cc + 1]; }
                if (mode == 2) { v0 = tanhf(v0 + aux0[cc]); v1 = tanhf(v1 + aux0[cc + 1]); }
                if (mode == 3) {
                    const float* p0 = aux0 + (size_t)(bb * 50 + jj) * N;
                    const float* p1 = aux1 + (size_t)(bb * 10 + ii) * N;
                    v0 += p0[cc] + p1[cc] + aux2[cc];
                    v1 += p0[cc + 1] + p1[cc + 1] + aux2[cc + 1];
                }
                if (mode == 4) {
                    const float* p0 = aux0 + (size_t)(bb * 10 + ii) * N;
                    v0 = tanhf(v0 + p0[cc]); v1 = tanhf(v1 + p0[cc + 1]);
                }
                if (out & 1)
                    *reinterpret_cast<float2*>(&C[(size_t)r * ldc + cc]) = make_float2(v0, v1);
                if (out & 2) {
                    bf16 h0 = __float2bfloat16_rn(v0), h1 = __float2bfloat16_rn(v1);
                    *reinterpret_cast<uint32_t*>(&Ch[(size_t)r * ldc + cc]) = pk2h(h0, h1);
                    *reinterpret_cast<uint32_t*>(&Cl[(size_t)r * ldc + cc]) =
                        pkbf(v0 - __bfloat162float(h0), v1 - __bfloat162float(h1));
                }
            }
        }
    }
}

// template wrapper (big GEMMs, modes 2/3/4)
template <int MODE, int OUT>
__global__ __launch_bounds__(256) void gemm_mma(
    const bf16* __restrict__ Ah, const bf16* __restrict__ Al, int lda,
    const bf16* __restrict__ Bh, const bf16* __restrict__ Bl, int ldb,
    float* __restrict__ C, bf16* __restrict__ Ch, bf16* __restrict__ Cl,
    int ldc, int M, int N, int K,
    const float* __restrict__ aux0, const float* __restrict__ aux1,
    const float* __restrict__ aux2)
{
    gemm_core(Ah, Al, lda, Bh, Bl, ldb, C, Ch, Cl, ldc, M, N, K,
              aux0, aux1, aux2, blockIdx.y * TBM, blockIdx.x * TBN, MODE, OUT);
}

// grouped wrapper (small GEMMs, modes 0/1)
struct GDesc {
    const bf16 *Ah, *Al, *Bh, *Bl;
    float* C; bf16 *Ch; bf16 *Cl;
    const float* aux0;
    int lda, ldb, ldc, M, N, K, mode, out, bx;
};
struct GParams { GDesc d[6]; int cum[7]; int nd; };

__global__ __launch_bounds__(256) void gemm_group(GParams P) {
    int g = 0;
    while (g + 1 < P.nd && (int)blockIdx.x >= P.cum[g + 1]) g++;
    const GDesc& D = P.d[g];
    int local = blockIdx.x - P.cum[g];
    int bxi = local % D.bx, byi = local / D.bx;
    gemm_core(D.Ah, D.Al, D.lda, D.Bh, D.Bl, D.ldb, D.C, D.Ch, D.Cl, D.ldc,
              D.M, D.N, D.K, D.aux0, nullptr, nullptr,
              byi * TBM, bxi * TBN, D.mode, D.out);
}

// ---------------- attention K/V pre-split ----------------
__global__ void attn_prep(const float* __restrict__ Cq3, const float* __restrict__ Hq3,
                          bf16* __restrict__ KHg, bf16* __restrict__ KLg,
                          bf16* __restrict__ VHg, bf16* __restrict__ VLg)
{
    const int n = blockIdx.x, b = blockIdx.y;
    const float* Hrow = Hq3 + (size_t)(b * NH_ + n) * 1200;
    const bf16 zb = __float2bfloat16_rn(0.f);

    for (int idx = threadIdx.x; idx < 4000; idx += 256) {
        int h = idx / 200, mm = (idx / 20) % 10, d = idx % 20;
        int m = b * 10 + mm;
        float kv = Cq3[m * 1200 + 400 + h * 20 + d] + Hrow[400 + h * 20 + d];
        bf16 hh = __float2bfloat16_rn(kv);
        size_t o = ((size_t)(n * 20 + h) * 640 + m) * 32 + d;
        KHg[o] = hh;
        KLg[o] = __float2bfloat16_rn(kv - __bfloat162float(hh));
    }
    for (int idx = threadIdx.x; idx < 2400; idx += 256) {
        int h = idx / 120, mm = (idx / 12) % 10, d = 20 + idx % 12;
        size_t o = ((size_t)(n * 20 + h) * 640 + b * 10 + mm) * 32 + d;
        KHg[o] = zb; KLg[o] = zb;
    }
    for (int idx = threadIdx.x; idx < 4000; idx += 256) {
        int h = idx / 200, d = (idx / 10) % 20, mm = idx % 10;
        int m = b * 10 + mm;
        float vv = Cq3[m * 1200 + 800 + h * 20 + d] + Hrow[800 + h * 20 + d];
        bf16 hh = __float2bfloat16_rn(vv);
        size_t o = ((size_t)(n * 20 + h) * 20 + d) * 640 + m;
        VHg[o] = hh;
        VLg[o] = __float2bfloat16_rn(vv - __bfloat162float(hh));
    }
}

// ---------------- tensor-core flash attention ----------------
__global__ __launch_bounds__(256) void attn_mma(
    const float* __restrict__ Cq3, const float* __restrict__ Hq3,
    const bf16* __restrict__ KHg, const bf16* __restrict__ KLg,
    const bf16* __restrict__ VHg, const bf16* __restrict__ VLg,
    bf16* __restrict__ Xoh, bf16* __restrict__ Xol)
{
    __shared__ __align__(16) bf16 sm[18944];
    bf16* QH = sm;               // [128][40]
    bf16* QL = sm + 5120;
    bf16* KH = sm;               // reuse after Q frags loaded
    bf16* KL = sm + 5120;
    bf16* VTH = sm + 10240;      // [32][136]
    bf16* VTL = sm + 14592;

    const int qt = blockIdx.x, n = blockIdx.y, h = blockIdx.z;
    const int tid = threadIdx.x, w = tid >> 5, lane = tid & 31;
    const float scale = 0.22360679774997896f;  // 1/sqrt(20)
    const bf16 zb = __float2bfloat16_rn(0.f);

    const bf16* Kbh = KHg + (size_t)(n * 20 + h) * 640 * 32;
    const bf16* Kbl = KLg + (size_t)(n * 20 + h) * 640 * 32;
    const bf16* Vbh = VHg + (size_t)(n * 20 + h) * 20 * 640;
    const bf16* Vbl = VLg + (size_t)(n * 20 + h) * 20 * 640;

    for (int idx = tid; idx < 128 * 32; idx += 256) {
        int r = idx >> 5, d = idx & 31;
        float v = 0.f;
        if (d < 20) {
            int l = qt * 128 + r;
            int qr = (l / NC_) * NH_ + n;
            v = (Cq3[l * 1200 + h * 20 + d] + Hq3[qr * 1200 + h * 20 + d]) * scale;
        }
        bf16 hh = __float2bfloat16_rn(v);
        QH[r * 40 + d] = hh;
        QL[r * 40 + d] = __float2bfloat16_rn(v - __bfloat162float(hh));
    }
    __syncthreads();

    const int mrow = ((lane >> 3) & 1) * 8 + (lane & 7);
    const int koff = (lane >> 4) * 8;

    uint32_t qh[2][4], ql[2][4];
    #pragma unroll
    for (int kc = 0; kc < 2; kc++) {
        uint32_t a = (uint32_t)(((w * 16 + mrow) * 40 + kc * 16 + koff) * 2);
        ldm4(qh[kc][0], qh[kc][1], qh[kc][2], qh[kc][3], s2u(QH) + a);
        ldm4(ql[kc][0], ql[kc][1], ql[kc][2], ql[kc][3], s2u(QL) + a);
    }
    __syncthreads();

    for (int idx = tid; idx < 12 * 136; idx += 256) {
        int d = 20 + idx / 136, k = idx % 136;
        VTH[d * 136 + k] = zb; VTL[d * 136 + k] = zb;
    }

    float O0[3][4];
    #pragma unroll
    for (int f = 0; f < 3; f++)
        #pragma unroll
        for (int e = 0; e < 4; e++) O0[f][e] = 0.f;
    float zl = 0.f, zh2 = 0.f;

    for (int kt = 0; kt < 5; kt++) {
        __syncthreads();
        for (int i = tid; i < 512; i += 256) {
            int kk = i >> 2, q = (i & 3) * 8;
            size_t src = (size_t)(kt * 128 + kk) * 32 + q;
            *reinterpret_cast<uint4*>(&KH[kk * 40 + q]) =
                *reinterpret_cast<const uint4*>(&Kbh[src]);
            *reinterpret_cast<uint4*>(&KL[kk * 40 + q]) =
                *reinterpret_cast<const uint4*>(&Kbl[src]);
        }
        for (int i = tid; i < 320; i += 256) {
            int d = i >> 4, cc = (i & 15) * 8;
            size_t src = (size_t)d * 640 + kt * 128 + cc;
            *reinterpret_cast<uint4*>(&VTH[d * 136 + cc]) =
                *reinterpret_cast<const uint4*>(&Vbh[src]);
            *reinterpret_cast<uint4*>(&VTL[d * 136 + cc]) =
                *reinterpret_cast<const uint4*>(&Vbl[src]);
        }
        __syncthreads();

        union { float f[16][4]; uint32_t u[16][4]; } SP;
        #pragma unroll
        for (int f = 0; f < 16; f++)
            #pragma unroll
            for (int e = 0; e < 4; e++) SP.f[f][e] = 0.f;

        #pragma unroll
        for (int g = 0; g < 8; g++) {
            uint32_t kh[2][4], kl[2][4];
            #pragma unroll
            for (int kc = 0; kc < 2; kc++) {
                uint32_t a = (uint32_t)(((g * 16 + mrow) * 40 + kc * 16 + koff) * 2);
                ldm4(kh[kc][0], kh[kc][1], kh[kc][2], kh[kc][3], s2u(KH) + a);
                ldm4(kl[kc][0], kl[kc][1], kl[kc][2], kl[kc][3], s2u(KL) + a);
            }
            #pragma unroll
            for (int kc = 0; kc < 2; kc++) {
                mma16816(SP.f[2 * g + 0], qh[kc], kh[kc][0], kh[kc][2]);
                mma16816(SP.f[2 * g + 0], qh[kc], kl[kc][0], kl[kc][2]);
                mma16816(SP.f[2 * g + 0], ql[kc], kh[kc][0], kh[kc][2]);
                mma16816(SP.f[2 * g + 1], qh[kc], kh[kc][1], kh[kc][3]);
                mma16816(SP.f[2 * g + 1], qh[kc], kl[kc][1], kl[kc][3]);
                mma16816(SP.f[2 * g + 1], ql[kc], kh[kc][1], kh[kc][3]);
            }
        }

        #pragma unroll
        for (int f = 0; f < 16; f++) {
            float e0 = __expf(SP.f[f][0]), e1 = __expf(SP.f[f][1]);
            float e2 = __expf(SP.f[f][2]), e3 = __expf(SP.f[f][3]);
            zl += e0 + e1; zh2 += e2 + e3;
            bf16 h0 = __float2bfloat16_rn(e0), h1 = __float2bfloat16_rn(e1);
            bf16 h2 = __float2bfloat16_rn(e2), h3 = __float2bfloat16_rn(e3);
            uint32_t ph01 = pk2h(h0, h1), ph23 = pk2h(h2, h3);
            uint32_t pl01 = pkbf(e0 - __bfloat162float(h0), e1 - __bfloat162float(h1));
            uint32_t pl23 = pkbf(e2 - __bfloat162float(h2), e3 - __bfloat162float(h3));
            SP.u[f][0] = ph01; SP.u[f][1] = ph23; SP.u[f][2] = pl01; SP.u[f][3] = pl23;
        }

        #pragma unroll
        for (int kc2 = 0; kc2 < 8; kc2++) {
            uint32_t ah[4] = { SP.u[2 * kc2][0], SP.u[2 * kc2][1],
                               SP.u[2 * kc2 + 1][0], SP.u[2 * kc2 + 1][1] };
            uint32_t al[4] = { SP.u[2 * kc2][2], SP.u[2 * kc2][3],
                               SP.u[2 * kc2 + 1][2], SP.u[2 * kc2 + 1][3] };
            uint32_t vh4[4], vl4[4], vh2[2], vl2[2];
            uint32_t a4 = (uint32_t)((mrow * 136 + kc2 * 16 + koff) * 2);
            uint32_t a2 = (uint32_t)(((16 + (lane & 7)) * 136 + kc2 * 16 + ((lane >> 3) & 1) * 8) * 2);
            ldm4(vh4[0], vh4[1], vh4[2], vh4[3], s2u(VTH) + a4);
            ldm4(vl4[0], vl4[1], vl4[2], vl4[3], s2u(VTL) + a4);
            ldm2(vh2[0], vh2[1], s2u(VTH) + a2);
            ldm2(vl2[0], vl2[1], s2u(VTL) + a2);
            mma16816(O0[0], ah, vh4[0], vh4[2]);
            mma16816(O0[0], ah, vl4[0], vl4[2]);
            mma16816(O0[0], al, vh4[0], vh4[2]);
            mma16816(O0[1], ah, vh4[1], vh4[3]);
            mma16816(O0[1], ah, vl4[1], vl4[3]);
            mma16816(O0[1], al, vh4[1], vh4[3]);
            mma16816(O0[2], ah, vh2[0], vh2[1]);
            mma16816(O0[2], ah, vl2[0], vl2[1]);
            mma16816(O0[2], al, vh2[0], vh2[1]);
        }
    }

    zl  += __shfl_xor_sync(0xffffffffu, zl, 1);
    zl  += __shfl_xor_sync(0xffffffffu, zl, 2);
    zh2 += __shfl_xor_sync(0xffffffffu, zh2, 1);
    zh2 += __shfl_xor_sync(0xffffffffu, zh2, 2);
    float izl = 1.f / zl, izh = 1.f / zh2;

    const int rowq = lane >> 2;
    #pragma unroll
    for (int f = 0; f < 3; f++) {
        int d0 = f * 8 + (lane & 3) * 2;
        if (d0 >= 20) continue;
        #pragma unroll
        for (int half = 0; half < 2; half++) {
            int lq = qt * 128 + w * 16 + rowq + half * 8;
            float v0 = O0[f][half * 2]     * (half ? izh : izl);
            float v1 = O0[f][half * 2 + 1] * (half ? izh : izl);
            size_t o = (size_t)(lq * NH_ + n) * 400 + h * 20 + d0;
            bf16 h0 = __float2bfloat16_rn(v0), h1 = __float2bfloat16_rn(v1);
            *reinterpret_cast<uint32_t*>(&Xoh[o]) = pk2h(h0, h1);
            *reinterpret_cast<uint32_t*>(&Xol[o]) =
                pkbf(v0 - __bfloat162float(h0), v1 - __bfloat162float(h1));
        }
    }
}

// ---------------- score + softmax ----------------
__global__ void score_kernel(const float* __restrict__ a2, const float* __restrict__ Wa3,
                             const float* __restrict__ ba3, float* __restrict__ s)
{
    int row = blockIdx.x * 8 + threadIdx.y;
    if (row >= MM) return;
    int lane = threadIdx.x;
    float acc = 0.f;
    for (int d = lane; d < 200; d += 32) acc += a2[(size_t)row * 200 + d] * Wa3[d];
    #pragma unroll
    for (int o = 16; o > 0; o >>= 1) acc += __shfl_xor_sync(0xffffffffu, acc, o);
    if (lane == 0) s[row] = acc + ba3[0];
}

__global__ void softmax_u_kernel(const float* __restrict__ s, const float* __restrict__ hall,
                                 float* __restrict__ u)
{
    __shared__ float a[NH_];
    int bi = blockIdx.x;
    if (threadIdx.x == 0) {
        float mx = -1e30f;
        for (int j = 0; j < NH_; j++) mx = fmaxf(mx, s[bi * NH_ + j]);
        float Z = 0.f;
        for (int j = 0; j < NH_; j++) { float e = __expf(s[bi * NH_ + j] - mx); a[j] = e; Z += e; }
        float iz = 1.f / Z;
        for (int j = 0; j < NH_; j++) a[j] *= iz;
    }
    __syncthreads();
    for (int d = threadIdx.x; d < 400; d += blockDim.x) {
        float acc = 0.f;
        for (int j = 0; j < NH_; j++)
            acc += a[j] * hall[((size_t)bi * NH_ + j) * 400 + d];
        u[(size_t)bi * 400 + d] = acc;
    }
}

// ---------------- launch ----------------
static inline dim3 mgrid(int M, int N) { return dim3((N + TBN - 1) / TBN, (M + TBM - 1) / TBM); }

extern "C" void kernel_launch(void* const* d_in, const int* in_sizes, int n_in,
                              void* d_out, int out_size)
{
    const float* h    = (const float*)d_in[0];
    const float* c    = (const float*)d_in[2];
    const float* W1   = (const float*)d_in[4];
    const float* b1   = (const float*)d_in[5];
    const float* W2   = (const float*)d_in[6];
    const float* b2   = (const float*)d_in[7];
    const float* W3   = (const float*)d_in[8];
    const float* b3   = (const float*)d_in[9];
    const float* Wa1  = (const float*)d_in[10];
    const float* ba1  = (const float*)d_in[11];
    const float* Wa2  = (const float*)d_in[12];
    const float* ba2  = (const float*)d_in[13];
    const float* Wa3  = (const float*)d_in[14];
    const float* ba3  = (const float*)d_in[15];
    const float* Wqkv = (const float*)d_in[16];
    const float* bqkv = (const float*)d_in[17];
    const float* Wo   = (const float*)d_in[18];
    const float* bo   = (const float*)d_in[19];
    float* u = (float*)d_out;

    float *Hq3, *Cq3, *T1, *T2, *tc, *CA, *hall, *a2, *sc;
    cudaGetSymbolAddress((void**)&Hq3,  g_Hq3);
    cudaGetSymbolAddress((void**)&Cq3,  g_Cq3);
    cudaGetSymbolAddress((void**)&T1,   g_T1);
    cudaGetSymbolAddress((void**)&T2,   g_T2);
    cudaGetSymbolAddress((void**)&tc,   g_tc);
    cudaGetSymbolAddress((void**)&CA,   g_CA);
    cudaGetSymbolAddress((void**)&hall, g_hall);
    cudaGetSymbolAddress((void**)&a2,   g_a2);
    cudaGetSymbolAddress((void**)&sc,   g_s);

    bf16 *bHcat_h, *bHcat_l, *bh_h, *bh_l, *bHs_h, *bHs_l, *bHp1_h, *bHp1_l;
    bf16 *bc_h, *bc_l, *bCc_h, *bCc_l, *bCs_h, *bCs_l;
    bf16 *bXo_h, *bXo_l, *bhall_h, *bhall_l, *ba1_h, *ba1_l;
    bf16 *bW1_h, *bW1_l, *bW2_h, *bW2_l, *bWqkv_h, *bWqkv_l, *bW3_h, *bW3_l;
    bf16 *bWa1_h, *bWa1_l, *bWa2_h, *bWa2_l, *bWoT_h, *bWoT_l, *bWm_h, *bWm_l;
    bf16 *KHg, *KLg, *VHg, *VLg;
    cudaGetSymbolAddress((void**)&bHcat_h, g_bHcat_h);  cudaGetSymbolAddress((void**)&bHcat_l, g_bHcat_l);
    cudaGetSymbolAddress((void**)&bh_h,    g_bh_h);     cudaGetSymbolAddress((void**)&bh_l,    g_bh_l);
    cudaGetSymbolAddress((void**)&bHs_h,   g_bHs_h);    cudaGetSymbolAddress((void**)&bHs_l,   g_bHs_l);
    cudaGetSymbolAddress((void**)&bHp1_h,  g_bHp1_h);   cudaGetSymbolAddress((void**)&bHp1_l,  g_bHp1_l);
    cudaGetSymbolAddress((void**)&bc_h,    g_bc_h);     cudaGetSymbolAddress((void**)&bc_l,    g_bc_l);
    cudaGetSymbolAddress((void**)&bCc_h,   g_bCc_h);    cudaGetSymbolAddress((void**)&bCc_l,   g_bCc_l);
    cudaGetSymbolAddress((void**)&bCs_h,   g_bCs_h);    cudaGetSymbolAddress((void**)&bCs_l,   g_bCs_l);
    cudaGetSymbolAddress((void**)&bXo_h,   g_bXo_h);    cudaGetSymbolAddress((void**)&bXo_l,   g_bXo_l);
    cudaGetSymbolAddress((void**)&bhall_h, g_bhall_h);  cudaGetSymbolAddress((void**)&bhall_l, g_bhall_l);
    cudaGetSymbolAddress((void**)&ba1_h,   g_ba1_h);    cudaGetSymbolAddress((void**)&ba1_l,   g_ba1_l);
    cudaGetSymbolAddress((void**)&bW1_h,   g_bW1_h);    cudaGetSymbolAddress((void**)&bW1_l,   g_bW1_l);
    cudaGetSymbolAddress((void**)&bW2_h,   g_bW2_h);    cudaGetSymbolAddress((void**)&bW2_l,   g_bW2_l);
    cudaGetSymbolAddress((void**)&bWqkv_h, g_bWqkv_h);  cudaGetSymbolAddress((void**)&bWqkv_l, g_bWqkv_l);
    cudaGetSymbolAddress((void**)&bW3_h,   g_bW3_h);    cudaGetSymbolAddress((void**)&bW3_l,   g_bW3_l);
    cudaGetSymbolAddress((void**)&bWa1_h,  g_bWa1_h);   cudaGetSymbolAddress((void**)&bWa1_l,  g_bWa1_l);
    cudaGetSymbolAddress((void**)&bWa2_h,  g_bWa2_h);   cudaGetSymbolAddress((void**)&bWa2_l,  g_bWa2_l);
    cudaGetSymbolAddress((void**)&bWoT_h,  g_bWoT_h);   cudaGetSymbolAddress((void**)&bWoT_l,  g_bWoT_l);
    cudaGetSymbolAddress((void**)&bWm_h,   g_bWm_h);    cudaGetSymbolAddress((void**)&bWm_l,   g_bWm_l);
    cudaGetSymbolAddress((void**)&KHg, g_KHg);  cudaGetSymbolAddress((void**)&KLg, g_KLg);
    cudaGetSymbolAddress((void**)&VHg, g_VHg);  cudaGetSymbolAddress((void**)&VLg, g_VLg);

    // (1) merged conversions
    ConvParams CP;
    const float* srcs[8] = { h, c, W1, W2, Wqkv, W3, Wa1, Wa2 };
    bf16* his[8] = { bh_h, bc_h, bW1_h, bW2_h, bWqkv_h, bW3_h, bWa1_h, bWa2_h };
    bf16* los[8] = { bh_l, bc_l, bW1_l, bW2_l, bWqkv_l, bW3_l, bWa1_l, bWa2_l };
    int ns[8] = { BNH * 400, LL * 400, 400 * 1600, 400 * 800, 1200 * 400,
                  400 * 800, 400 * 800, 200 * 400 };
    int cum = 0;
    for (int i = 0; i < 8; i++) { CP.src[i] = srcs[i]; CP.hi[i] = his[i]; CP.lo[i] = los[i];
                                  CP.cum[i] = cum; cum += ns[i]; }
    CP.cum[8] = cum;
    conv_all_kernel<<<(cum + 255) / 256, 256>>>(CP);

    // (2) Hcat gather + Wo transpose-split, one launch
    prep2_kernel<<<HC_BLOCKS + TR_BLOCKS, 256>>>(bh_h, bh_l, bHcat_h, bHcat_l,
                                                 Wo, bWoT_h, bWoT_l);

    // (3) grouped GEMM launch 1: independent small GEMMs
    {
        GParams G; int cumb = 0; int gi = 0;
        auto add = [&](const bf16* Ah, const bf16* Al, int lda,
                       const bf16* Bh, const bf16* Bl, int ldb,
                       float* C, bf16* Ch, bf16* Cl, int ldc,
                       int M, int N, int K, int mode, int out, const float* aux0) {
            GDesc& D = G.d[gi];
            D.Ah = Ah; D.Al = Al; D.Bh = Bh; D.Bl = Bl;
            D.C = C; D.Ch = Ch; D.Cl = Cl; D.aux0 = aux0;
            D.lda = lda; D.ldb = ldb; D.ldc = ldc; D.M = M; D.N = N; D.K = K;
            D.mode = mode; D.out = out;
            D.bx = (N + TBN - 1) / TBN;
            int by = (M + TBM - 1) / TBM;
            G.cum[gi] = cumb; cumb += D.bx * by; gi++;
        };
        add(bHcat_h, bHcat_l, 1200, bW1_h, bW1_l, 1600, nullptr, bHp1_h, bHp1_l, 400,
            BNH, 400, 1200, 0, 2, nullptr);                                   // Hp1
        add(bh_h, bh_l, 400, bW2_h + 400, bW2_l + 400, 800, nullptr, bHs_h, bHs_l, 400,
            BNH, 400, 400, 0, 2, nullptr);                                    // Hs
        add(bc_h, bc_l, 400, bW1_h + 1200, bW1_l + 1200, 1600, nullptr, bCc_h, bCc_l, 400,
            LL, 400, 400, 0, 2, nullptr);                                     // Cc
        add(bc_h, bc_l, 400, bW2_h, bW2_l, 800, nullptr, bCs_h, bCs_l, 400,
            LL, 400, 400, 1, 2, b2);                                          // Cs
        add(bc_h, bc_l, 400, bWa1_h + 400, bWa1_l + 400, 800, CA, nullptr, nullptr, 400,
            LL, 400, 400, 1, 1, ba1);                                         // CA
        add(bW3_h + 400, bW3_l + 400, 800, bWoT_h, bWoT_l, 400, nullptr, bWm_h, bWm_l, 400,
            400, 400, 400, 0, 2, nullptr);                                    // Wm
        G.cum[gi] = cumb; G.nd = gi;
        gemm_group<<<cumb, 256>>>(G);
    }

    // (4) grouped GEMM launch 2: dependent small GEMMs
    {
        GParams G; int cumb = 0; int gi = 0;
        auto add = [&](const bf16* Ah, const bf16* Al, int lda,
                       const bf16* Bh, const bf16* Bl, int ldb,
                       float* C, int ldc, int M, int N, int K, int mode, const float* aux0) {
            GDesc& D = G.d[gi];
            D.Ah = Ah; D.Al = Al; D.Bh = Bh; D.Bl = Bl;
            D.C = C; D.Ch = nullptr; D.Cl = nullptr; D.aux0 = aux0;
            D.lda = lda; D.ldb = ldb; D.ldc = ldc; D.M = M; D.N = N; D.K = K;
            D.mode = mode; D.out = 1;
            D.bx = (N + TBN - 1) / TBN;
            int by = (M + TBM - 1) / TBM;
            G.cum[gi] = cumb; cumb += D.bx * by; gi++;
        };
        add(bHp1_h, bHp1_l, 400, bW3_h, bW3_l, 800, T1, 400, BNH, 400, 400, 0, nullptr);      // T1
        add(bHs_h, bHs_l, 400, bWqkv_h, bWqkv_l, 400, Hq3, 1200, BNH, 1200, 400, 0, nullptr); // Hq3
        add(bCs_h, bCs_l, 400, bWqkv_h, bWqkv_l, 400, Cq3, 1200, LL, 1200, 400, 1, bqkv);     // Cq3
        add(bCc_h, bCc_l, 400, bW3_h, bW3_l, 800, T2, 400, LL, 400, 400, 0, nullptr);         // T2
        G.cum[gi] = cumb; G.nd = gi;
        gemm_group<<<cumb, 256>>>(G);
    }

    // (5) attention K/V pre-split
    attn_prep<<<dim3(NH_, BB), 256>>>(Cq3, Hq3, KHg, KLg, VHg, VLg);

    // (6) tensor-core flash attention  <-- ncu capture slot
    attn_mma<<<dim3(5, NH_, NHEAD), 256>>>(Cq3, Hq3, KHg, KLg, VHg, VLg, bXo_h, bXo_l);

    // (7) tc (fast warp-reduction version; only needed by hall)
    tc_kernel<<<50, 256>>>(b1, bo, b3, W3, tc);

    // (8-10) big GEMMs
    gemm_mma<3, 3><<<mgrid(MM, 400), 256>>>(bXo_h, bXo_l, 400, bWm_h, bWm_l, 400,
        hall, bhall_h, bhall_l, 400, MM, 400, 400, T1, T2, tc);
    gemm_mma<4, 2><<<mgrid(MM, 400), 256>>>(bhall_h, bhall_l, 400, bWa1_h, bWa1_l, 800,
        nullptr, ba1_h, ba1_l, 400, MM, 400, 400, CA, nullptr, nullptr);
    gemm_mma<2, 1><<<mgrid(MM, 200), 256>>>(ba1_h, ba1_l, 400, bWa2_h, bWa2_l, 400,
        a2, nullptr, nullptr, 200, MM, 200, 400, ba2, nullptr, nullptr);

    // (11-12) scoring + softmax + weighted sum
    score_kernel<<<MM / 8, dim3(32, 8)>>>(a2, Wa3, ba3, sc);
    softmax_u_kernel<<<LL, 128>>>(sc, hall, u);
}